// round 2
// baseline (speedup 1.0000x reference)
#include <cuda_runtime.h>

#define Bg 128
#define Ng 2048
#define Dd 256
#define Hh 16
#define Kk 32
#define Rr 16
#define BN (Bg*Ng)

// scratch (static device arrays; no allocation)
__device__ unsigned g_pooled_enc[Bg*Dd];
__device__ float    g_keys [BN*Kk];     // [B,N,K]
__device__ float    g_evals[BN*Rr];     // [B,N,R]
__device__ float    g_q    [Bg*2*Hh*Kk];
__device__ float    g_embed[Bg*2*Hh*Rr];

__device__ __forceinline__ unsigned encf(float f) {
    unsigned u = __float_as_uint(f);
    return (u & 0x80000000u) ? ~u : (u | 0x80000000u);
}
__device__ __forceinline__ float decf(unsigned u) {
    u = (u & 0x80000000u) ? (u & 0x7FFFFFFFu) : ~u;
    return __uint_as_float(u);
}

__global__ void k_init() {
    g_pooled_enc[blockIdx.x * 256 + threadIdx.x] = 0u;  // encoded minimum
}

// ---------------------------------------------------------------------------
// K2: fused  keys|e = x @ [Wk;We]^T   +  per-graph column max -> pooled
// grid 2048 blocks (128 rows each), 256 threads, thread tile 4x6
// ---------------------------------------------------------------------------
#define SMEM_GEMM ((48*256 + 32*129 + 128*49 + 256) * 4)
__global__ void __launch_bounds__(256, 2)
k_gemm(const float* __restrict__ inp, const float* __restrict__ Wk,
       const float* __restrict__ We) {
    extern __shared__ float sm[];
    float* Ws = sm;                 // [48][256]
    float* As = Ws + 48*256;        // [32][129]
    float* Cs = As + 32*129;        // [128][49]
    float* Mb = Cs + 128*49;        // [32][8]

    const int t  = threadIdx.x;
    const int r0 = blockIdx.x * 128;
    const int b  = blockIdx.x >> 4;

    for (int idx = t; idx < 48*256; idx += 256)
        Ws[idx] = (idx < 32*256) ? Wk[idx] : We[idx - 32*256];

    const int i  = t & 31;   // row lane (reads)
    const int j  = t >> 5;   // col group (reads)
    const int c  = t & 31;   // column within k-chunk (loads)
    const int rr = t >> 5;   // row start (loads)

    float acc[4][6];
#pragma unroll
    for (int u = 0; u < 4; u++)
#pragma unroll
        for (int v = 0; v < 6; v++) acc[u][v] = 0.f;

    const float* xbase = inp + (size_t)r0 * 256;
    const float NEG_INF = __int_as_float(0xff800000);

    for (int kc = 0; kc < 8; kc++) {
        __syncthreads();
        float mx = NEG_INF;
#pragma unroll
        for (int p = 0; p < 16; p++) {
            const int row = rr + 8 * p;
            const float val = xbase[(size_t)row * 256 + kc * 32 + c];
            As[c * 129 + row] = val;
            mx = fmaxf(mx, val);
        }
        Mb[c * 8 + rr] = mx;
        __syncthreads();
        if (t < 32) {
            float m = Mb[t * 8];
#pragma unroll
            for (int p = 1; p < 8; p++) m = fmaxf(m, Mb[t * 8 + p]);
            atomicMax(&g_pooled_enc[b * 256 + kc * 32 + t], encf(m));
        }
#pragma unroll
        for (int k = 0; k < 32; k++) {
            float a[4], w[6];
#pragma unroll
            for (int u = 0; u < 4; u++) a[u] = As[k * 129 + i + 32 * u];
#pragma unroll
            for (int v = 0; v < 6; v++) w[v] = Ws[(j * 6 + v) * 256 + kc * 32 + k];
#pragma unroll
            for (int u = 0; u < 4; u++)
#pragma unroll
                for (int v = 0; v < 6; v++)
                    acc[u][v] = fmaf(a[u], w[v], acc[u][v]);
        }
    }
    __syncthreads();
#pragma unroll
    for (int u = 0; u < 4; u++)
#pragma unroll
        for (int v = 0; v < 6; v++)
            Cs[(i + 32 * u) * 49 + (j * 6 + v)] = acc[u][v];
    __syncthreads();
    for (int idx = t; idx < 128 * 32; idx += 256) {
        const int row = idx >> 5, col = idx & 31;
        g_keys[(size_t)(r0 + row) * 32 + col] = Cs[row * 49 + col];
    }
    for (int idx = t; idx < 128 * 16; idx += 256) {
        const int row = idx >> 4, col = idx & 15;
        g_evals[(size_t)(r0 + row) * 16 + col] = Cs[row * 49 + 32 + col];
    }
}

// ---------------------------------------------------------------------------
// K3: q[b, v*512 + h*32 + k] = pooled[b] . Wq_v[h*32+k]
// ---------------------------------------------------------------------------
__global__ void k_q(const float* __restrict__ Wq0, const float* __restrict__ Wq1) {
    __shared__ float ps[256];
    const int b = blockIdx.x, t = threadIdx.x;
    ps[t] = decf(g_pooled_enc[b * 256 + t]);
    __syncthreads();
#pragma unroll
    for (int g = 0; g < 4; g++) {
        const int o = g * 256 + t;   // 0..1023
        const float* wrow = (o < 512) ? (Wq0 + (size_t)o * 256)
                                      : (Wq1 + (size_t)(o - 512) * 256);
        const float4* w4 = (const float4*)wrow;
        float acc = 0.f;
#pragma unroll 8
        for (int k4 = 0; k4 < 64; k4++) {
            const float4 w = w4[k4];
            acc = fmaf(ps[4*k4+0], w.x, acc);
            acc = fmaf(ps[4*k4+1], w.y, acc);
            acc = fmaf(ps[4*k4+2], w.z, acc);
            acc = fmaf(ps[4*k4+3], w.w, acc);
        }
        g_q[b * 1024 + o] = acc;
    }
}

// ---------------------------------------------------------------------------
// K4: per (graph b, variant v): logits -> softmax -> att @ e
// grid (128, 2), 256 threads. logits for all 16 heads kept in SMEM.
// ---------------------------------------------------------------------------
#define SMEM_ATTN ((16*2049 + 16*33 + 64*33 + 64*17) * 4)
__global__ void __launch_bounds__(256, 1)
k_attn() {
    extern __shared__ float sm[];
    float* logits = sm;                    // [16][2049]
    float* qs     = logits + 16 * 2049;    // [16][33]
    float* ks     = qs + 16 * 33;          // [64][33]
    float* es     = ks + 64 * 33;          // [64][17]

    const int b = blockIdx.x, v = blockIdx.y, t = threadIdx.x;

    for (int idx = t; idx < 512; idx += 256)
        qs[(idx >> 5) * 33 + (idx & 31)] = g_q[b * 1024 + v * 512 + idx];
    __syncthreads();

    const int h  = t & 15;
    const int nb = t >> 4;
    const float* keysb = g_keys + (size_t)b * Ng * 32;

    // phase 1: logits[h][n] = q[h] . keys[n]
    for (int ch = 0; ch < 32; ch++) {
        const int n0 = ch * 64;
        for (int idx = t; idx < 2048; idx += 256)
            ks[(idx >> 5) * 33 + (idx & 31)] = keysb[(size_t)n0 * 32 + idx];
        __syncthreads();
#pragma unroll
        for (int ii = 0; ii < 4; ii++) {
            const int nl = nb + 16 * ii;
            float acc = 0.f;
#pragma unroll
            for (int k = 0; k < 32; k++)
                acc = fmaf(qs[h * 33 + k], ks[nl * 33 + k], acc);
            logits[h * 2049 + n0 + nl] = acc;
        }
        __syncthreads();
    }

    // phase 2: softmax over n per head (one warp handles 2 heads)
    const int warp = t >> 5, lane = t & 31;
    for (int hh = warp; hh < 16; hh += 8) {
        float* L = logits + hh * 2049;
        float m = __int_as_float(0xff800000);
        for (int n = lane; n < 2048; n += 32) m = fmaxf(m, L[n]);
#pragma unroll
        for (int o = 16; o; o >>= 1) m = fmaxf(m, __shfl_xor_sync(0xffffffffu, m, o));
        float s = 0.f;
        for (int n = lane; n < 2048; n += 32) {
            const float e = __expf(L[n] - m);
            L[n] = e;
            s += e;
        }
#pragma unroll
        for (int o = 16; o; o >>= 1) s += __shfl_xor_sync(0xffffffffu, s, o);
        const float inv = 1.f / s;
        for (int n = lane; n < 2048; n += 32) L[n] *= inv;
    }
    __syncthreads();

    // phase 3: embed[h][r] = sum_n att[h][n] * e[n][r]
    const int r = t & 15, h3 = t >> 4;
    const float* eb = g_evals + (size_t)b * Ng * 16;
    float acc = 0.f;
    for (int ch = 0; ch < 32; ch++) {
        const int n0 = ch * 64;
        for (int idx = t; idx < 1024; idx += 256)
            es[(idx >> 4) * 17 + (idx & 15)] = eb[(size_t)n0 * 16 + idx];
        __syncthreads();
#pragma unroll
        for (int nl = 0; nl < 64; nl++)
            acc = fmaf(logits[h3 * 2049 + n0 + nl], es[nl * 17 + r], acc);
        __syncthreads();
    }
    g_embed[((b * 2 + v) * 16 + h3) * 16 + r] = acc;
}

// ---------------------------------------------------------------------------
// K5: out[b][d] = leaky( (embed0-embed1)[b] . Wout[d] + bout[d] )
// ---------------------------------------------------------------------------
__global__ void k_out(const float* __restrict__ Wout, const float* __restrict__ bout,
                      float* __restrict__ out) {
    __shared__ float dx[256];
    const int b = blockIdx.x, t = threadIdx.x;
    dx[t] = g_embed[b * 512 + t] - g_embed[b * 512 + 256 + t];
    __syncthreads();
    float acc = bout[t];
    const float4* w4 = (const float4*)(Wout + (size_t)t * 256);
#pragma unroll 8
    for (int k4 = 0; k4 < 64; k4++) {
        const float4 w = w4[k4];
        acc = fmaf(dx[4*k4+0], w.x, acc);
        acc = fmaf(dx[4*k4+1], w.y, acc);
        acc = fmaf(dx[4*k4+2], w.z, acc);
        acc = fmaf(dx[4*k4+3], w.w, acc);
    }
    out[b * 256 + t] = acc >= 0.f ? acc : 0.01f * acc;
}

extern "C" void kernel_launch(void* const* d_in, const int* in_sizes, int n_in,
                              void* d_out, int out_size) {
    const float* inp  = (const float*)d_in[0];
    // d_in[1] = batch_ids (int32): setup guarantees row i -> graph i/N; unused.
    const float* Wk   = (const float*)d_in[2];
    const float* Wq0  = (const float*)d_in[3];
    const float* Wq1  = (const float*)d_in[4];
    const float* We   = (const float*)d_in[5];
    const float* Wout = (const float*)d_in[6];
    const float* bout = (const float*)d_in[7];
    float* out = (float*)d_out;

    cudaFuncSetAttribute(k_gemm, cudaFuncAttributeMaxDynamicSharedMemorySize, SMEM_GEMM);
    cudaFuncSetAttribute(k_attn, cudaFuncAttributeMaxDynamicSharedMemorySize, SMEM_ATTN);

    k_init<<<128, 256>>>();
    k_gemm<<<BN / 128, 256, SMEM_GEMM>>>(inp, Wk, We);
    k_q<<<Bg, 256>>>(Wq0, Wq1);
    k_attn<<<dim3(Bg, 2), 256, SMEM_ATTN>>>();
    k_out<<<Bg, 256>>>(Wout, bout, out);
}

// round 3
// speedup vs baseline: 1.6063x; 1.6063x over previous
#include <cuda_runtime.h>

#define Bg 128
#define Ng 2048
#define Dd 256
#define Hh 16
#define Kk 32
#define Rr 16
#define BN (Bg*Ng)
#define NCHUNK 8
#define CHUNK 256

// scratch (static device arrays; no allocation)
__device__ unsigned g_pooled_enc[Bg*Dd];
__device__ float    g_keys [BN*Kk];     // [B,N,K]
__device__ float    g_evals[BN*Rr];     // [B,N,R]
__device__ float    g_q    [Bg*2*Hh*Kk];
__device__ float    g_embed[Bg*2*Hh*Rr];
__device__ float    g_part [Bg*NCHUNK*32*18];   // per (b,chunk,vh): m,s,acc[16]

__device__ __forceinline__ unsigned encf(float f) {
    unsigned u = __float_as_uint(f);
    return (u & 0x80000000u) ? ~u : (u | 0x80000000u);
}
__device__ __forceinline__ float decf(unsigned u) {
    u = (u & 0x80000000u) ? (u & 0x7FFFFFFFu) : ~u;
    return __uint_as_float(u);
}

__global__ void k_init() {
    g_pooled_enc[blockIdx.x * 256 + threadIdx.x] = 0u;  // encoded minimum
}

// ---------------------------------------------------------------------------
// K2: fused  keys|e = x @ [Wk;We]^T   +  per-graph column max -> pooled
// ---------------------------------------------------------------------------
#define SMEM_GEMM ((48*256 + 32*129 + 128*49 + 256) * 4)
__global__ void __launch_bounds__(256, 2)
k_gemm(const float* __restrict__ inp, const float* __restrict__ Wk,
       const float* __restrict__ We) {
    extern __shared__ float sm[];
    float* Ws = sm;                 // [48][256]
    float* As = Ws + 48*256;        // [32][129]
    float* Cs = As + 32*129;        // [128][49]
    float* Mb = Cs + 128*49;        // [32][8]

    const int t  = threadIdx.x;
    const int r0 = blockIdx.x * 128;
    const int b  = blockIdx.x >> 4;

    for (int idx = t; idx < 48*256; idx += 256)
        Ws[idx] = (idx < 32*256) ? Wk[idx] : We[idx - 32*256];

    const int i  = t & 31;
    const int j  = t >> 5;
    const int c  = t & 31;
    const int rr = t >> 5;

    float acc[4][6];
#pragma unroll
    for (int u = 0; u < 4; u++)
#pragma unroll
        for (int v = 0; v < 6; v++) acc[u][v] = 0.f;

    const float* xbase = inp + (size_t)r0 * 256;
    const float NEG_INF = __int_as_float(0xff800000);

    for (int kc = 0; kc < 8; kc++) {
        __syncthreads();
        float mx = NEG_INF;
#pragma unroll
        for (int p = 0; p < 16; p++) {
            const int row = rr + 8 * p;
            const float val = xbase[(size_t)row * 256 + kc * 32 + c];
            As[c * 129 + row] = val;
            mx = fmaxf(mx, val);
        }
        Mb[c * 8 + rr] = mx;
        __syncthreads();
        if (t < 32) {
            float m = Mb[t * 8];
#pragma unroll
            for (int p = 1; p < 8; p++) m = fmaxf(m, Mb[t * 8 + p]);
            atomicMax(&g_pooled_enc[b * 256 + kc * 32 + t], encf(m));
        }
#pragma unroll
        for (int k = 0; k < 32; k++) {
            float a[4], w[6];
#pragma unroll
            for (int u = 0; u < 4; u++) a[u] = As[k * 129 + i + 32 * u];
#pragma unroll
            for (int v = 0; v < 6; v++) w[v] = Ws[(j * 6 + v) * 256 + kc * 32 + k];
#pragma unroll
            for (int u = 0; u < 4; u++)
#pragma unroll
                for (int v = 0; v < 6; v++)
                    acc[u][v] = fmaf(a[u], w[v], acc[u][v]);
        }
    }
    __syncthreads();
#pragma unroll
    for (int u = 0; u < 4; u++)
#pragma unroll
        for (int v = 0; v < 6; v++)
            Cs[(i + 32 * u) * 49 + (j * 6 + v)] = acc[u][v];
    __syncthreads();
    for (int idx = t; idx < 128 * 32; idx += 256) {
        const int row = idx >> 5, col = idx & 31;
        g_keys[(size_t)(r0 + row) * 32 + col] = Cs[row * 49 + col];
    }
    for (int idx = t; idx < 128 * 16; idx += 256) {
        const int row = idx >> 4, col = idx & 15;
        g_evals[(size_t)(r0 + row) * 16 + col] = Cs[row * 49 + 32 + col];
    }
}

// ---------------------------------------------------------------------------
// K3: q[b, vh*32 + k] = pooled[b] . Wq_v[h*32+k]   (vh = v*16+h)
// ---------------------------------------------------------------------------
__global__ void k_q(const float* __restrict__ Wq0, const float* __restrict__ Wq1) {
    __shared__ float ps[256];
    const int b = blockIdx.x, t = threadIdx.x;
    ps[t] = decf(g_pooled_enc[b * 256 + t]);
    __syncthreads();
#pragma unroll
    for (int g = 0; g < 4; g++) {
        const int o = g * 256 + t;
        const float* wrow = (o < 512) ? (Wq0 + (size_t)o * 256)
                                      : (Wq1 + (size_t)(o - 512) * 256);
        const float4* w4 = (const float4*)wrow;
        float acc = 0.f;
#pragma unroll 8
        for (int k4 = 0; k4 < 64; k4++) {
            const float4 w = w4[k4];
            acc = fmaf(ps[4*k4+0], w.x, acc);
            acc = fmaf(ps[4*k4+1], w.y, acc);
            acc = fmaf(ps[4*k4+2], w.z, acc);
            acc = fmaf(ps[4*k4+3], w.w, acc);
        }
        g_q[b * 1024 + o] = acc;
    }
}

// ---------------------------------------------------------------------------
// K4a: split-softmax partials. grid (128 graphs, 8 chunks), 256 threads.
// Each warp owns 4 (v,h) pairs; 32 lanes cover the 256-token chunk.
// Register-resident logits -> warp softmax -> fused att@e accumulation.
// ---------------------------------------------------------------------------
#define KS_STRIDE 36
#define ES_STRIDE 20
#define SMEM_ATTN ((CHUNK*KS_STRIDE + CHUNK*ES_STRIDE + 32*32) * 4)

__global__ void __launch_bounds__(256, 2)
k_attn_part() {
    extern __shared__ float sm[];
    float* ks = sm;                        // [256][36]
    float* es = ks + CHUNK * KS_STRIDE;    // [256][20]
    float* qs = es + CHUNK * ES_STRIDE;    // [32][32]

    const int b = blockIdx.x, ch = blockIdx.y, t = threadIdx.x;
    const int n0 = ch * CHUNK;
    const float* keysb = g_keys  + ((size_t)b * Ng + n0) * 32;
    const float* eb    = g_evals + ((size_t)b * Ng + n0) * 16;

    // stage keys [256][32] as float4, padded stride 36
    for (int idx = t; idx < CHUNK * 8; idx += 256) {
        const int n = idx >> 3, k4 = idx & 7;
        ((float4*)(ks + n * KS_STRIDE))[k4] = ((const float4*)keysb)[idx];
    }
    // stage evals [256][16] as float4, padded stride 20
    for (int idx = t; idx < CHUNK * 4; idx += 256) {
        const int n = idx >> 2, r4 = idx & 3;
        ((float4*)(es + n * ES_STRIDE))[r4] = ((const float4*)eb)[idx];
    }
    // stage q [32 vh][32 k]
    for (int idx = t; idx < 1024; idx += 256)
        qs[idx] = g_q[b * 1024 + idx];
    __syncthreads();

    const int g  = t & 31;   // lane: n = g + 32*i
    const int vq = t >> 5;   // warp: vh = vq*4 + vv

    // phase 1: logits
    float l[4][8];
#pragma unroll
    for (int vv = 0; vv < 4; vv++)
#pragma unroll
        for (int i = 0; i < 8; i++) l[vv][i] = 0.f;

#pragma unroll
    for (int k4 = 0; k4 < 8; k4++) {
        float4 q4[4];
#pragma unroll
        for (int vv = 0; vv < 4; vv++)
            q4[vv] = ((const float4*)(qs + (vq * 4 + vv) * 32))[k4];
#pragma unroll
        for (int i = 0; i < 8; i++) {
            const float4 kv = ((const float4*)(ks + (g + 32 * i) * KS_STRIDE))[k4];
#pragma unroll
            for (int vv = 0; vv < 4; vv++) {
                l[vv][i] = fmaf(q4[vv].x, kv.x, l[vv][i]);
                l[vv][i] = fmaf(q4[vv].y, kv.y, l[vv][i]);
                l[vv][i] = fmaf(q4[vv].z, kv.z, l[vv][i]);
                l[vv][i] = fmaf(q4[vv].w, kv.w, l[vv][i]);
            }
        }
    }

    // phase 2: warp softmax (max, exp, sum) per vv
    float m[4], s[4];
#pragma unroll
    for (int vv = 0; vv < 4; vv++) {
        float mx = l[vv][0];
#pragma unroll
        for (int i = 1; i < 8; i++) mx = fmaxf(mx, l[vv][i]);
#pragma unroll
        for (int o = 16; o; o >>= 1) mx = fmaxf(mx, __shfl_xor_sync(0xffffffffu, mx, o));
        m[vv] = mx;
        float ss = 0.f;
#pragma unroll
        for (int i = 0; i < 8; i++) {
            const float e = __expf(l[vv][i] - mx);
            l[vv][i] = e;           // l now holds exp weights
            ss += e;
        }
#pragma unroll
        for (int o = 16; o; o >>= 1) ss += __shfl_xor_sync(0xffffffffu, ss, o);
        s[vv] = ss;
    }

    // phase 3: acc[vv][r] = sum_n e * evals[n][r]
    float acc[4][16];
#pragma unroll
    for (int vv = 0; vv < 4; vv++)
#pragma unroll
        for (int r = 0; r < 16; r++) acc[vv][r] = 0.f;

#pragma unroll
    for (int i = 0; i < 8; i++) {
        const float4* erow = (const float4*)(es + (g + 32 * i) * ES_STRIDE);
        float4 e0 = erow[0], e1 = erow[1], e2 = erow[2], e3 = erow[3];
#pragma unroll
        for (int vv = 0; vv < 4; vv++) {
            const float ev = l[vv][i];
            acc[vv][0]  = fmaf(ev, e0.x, acc[vv][0]);
            acc[vv][1]  = fmaf(ev, e0.y, acc[vv][1]);
            acc[vv][2]  = fmaf(ev, e0.z, acc[vv][2]);
            acc[vv][3]  = fmaf(ev, e0.w, acc[vv][3]);
            acc[vv][4]  = fmaf(ev, e1.x, acc[vv][4]);
            acc[vv][5]  = fmaf(ev, e1.y, acc[vv][5]);
            acc[vv][6]  = fmaf(ev, e1.z, acc[vv][6]);
            acc[vv][7]  = fmaf(ev, e1.w, acc[vv][7]);
            acc[vv][8]  = fmaf(ev, e2.x, acc[vv][8]);
            acc[vv][9]  = fmaf(ev, e2.y, acc[vv][9]);
            acc[vv][10] = fmaf(ev, e2.z, acc[vv][10]);
            acc[vv][11] = fmaf(ev, e2.w, acc[vv][11]);
            acc[vv][12] = fmaf(ev, e3.x, acc[vv][12]);
            acc[vv][13] = fmaf(ev, e3.y, acc[vv][13]);
            acc[vv][14] = fmaf(ev, e3.z, acc[vv][14]);
            acc[vv][15] = fmaf(ev, e3.w, acc[vv][15]);
        }
    }

    // warp-reduce acc, write partials
#pragma unroll
    for (int vv = 0; vv < 4; vv++)
#pragma unroll
        for (int r = 0; r < 16; r++) {
            float a = acc[vv][r];
#pragma unroll
            for (int o = 16; o; o >>= 1) a += __shfl_xor_sync(0xffffffffu, a, o);
            acc[vv][r] = a;
        }

    if (g == 0) {
        float* p = g_part + (((size_t)(b * NCHUNK + ch) * 32) + vq * 4) * 18;
#pragma unroll
        for (int vv = 0; vv < 4; vv++) {
            p[vv * 18 + 0] = m[vv];
            p[vv * 18 + 1] = s[vv];
#pragma unroll
            for (int r = 0; r < 16; r++) p[vv * 18 + 2 + r] = acc[vv][r];
        }
    }
}

// ---------------------------------------------------------------------------
// K4b: combine partials across chunks. grid 128, 32 threads (1 per vh).
// ---------------------------------------------------------------------------
__global__ void k_attn_red() {
    const int b = blockIdx.x, vh = threadIdx.x;
    const float* base = g_part + (size_t)b * NCHUNK * 32 * 18 + vh * 18;
    float M = __int_as_float(0xff800000);
#pragma unroll
    for (int c = 0; c < NCHUNK; c++) M = fmaxf(M, base[c * 32 * 18]);
    float S = 0.f, acc[16];
#pragma unroll
    for (int r = 0; r < 16; r++) acc[r] = 0.f;
#pragma unroll
    for (int c = 0; c < NCHUNK; c++) {
        const float* p = base + c * 32 * 18;
        const float w = __expf(p[0] - M);
        S = fmaf(p[1], w, S);
#pragma unroll
        for (int r = 0; r < 16; r++) acc[r] = fmaf(p[2 + r], w, acc[r]);
    }
    const float inv = 1.f / S;
#pragma unroll
    for (int r = 0; r < 16; r++)
        g_embed[b * 512 + vh * 16 + r] = acc[r] * inv;
}

// ---------------------------------------------------------------------------
// K5: out = leaky( (embed0-embed1) @ Wout^T + bout )
// ---------------------------------------------------------------------------
__global__ void k_out(const float* __restrict__ Wout, const float* __restrict__ bout,
                      float* __restrict__ out) {
    __shared__ float dx[256];
    const int b = blockIdx.x, t = threadIdx.x;
    dx[t] = g_embed[b * 512 + t] - g_embed[b * 512 + 256 + t];
    __syncthreads();
    float acc = bout[t];
    const float4* w4 = (const float4*)(Wout + (size_t)t * 256);
#pragma unroll 8
    for (int k4 = 0; k4 < 64; k4++) {
        const float4 w = w4[k4];
        acc = fmaf(dx[4*k4+0], w.x, acc);
        acc = fmaf(dx[4*k4+1], w.y, acc);
        acc = fmaf(dx[4*k4+2], w.z, acc);
        acc = fmaf(dx[4*k4+3], w.w, acc);
    }
    out[b * 256 + t] = acc >= 0.f ? acc : 0.01f * acc;
}

extern "C" void kernel_launch(void* const* d_in, const int* in_sizes, int n_in,
                              void* d_out, int out_size) {
    const float* inp  = (const float*)d_in[0];
    const float* Wk   = (const float*)d_in[2];
    const float* Wq0  = (const float*)d_in[3];
    const float* Wq1  = (const float*)d_in[4];
    const float* We   = (const float*)d_in[5];
    const float* Wout = (const float*)d_in[6];
    const float* bout = (const float*)d_in[7];
    float* out = (float*)d_out;

    cudaFuncSetAttribute(k_gemm, cudaFuncAttributeMaxDynamicSharedMemorySize, SMEM_GEMM);
    cudaFuncSetAttribute(k_attn_part, cudaFuncAttributeMaxDynamicSharedMemorySize, SMEM_ATTN);

    k_init<<<128, 256>>>();
    k_gemm<<<BN / 128, 256, SMEM_GEMM>>>(inp, Wk, We);
    k_q<<<Bg, 256>>>(Wq0, Wq1);
    k_attn_part<<<dim3(Bg, NCHUNK), 256, SMEM_ATTN>>>();
    k_attn_red<<<Bg, 32>>>();
    k_out<<<Bg, 256>>>(Wout, bout, out);
}

// round 5
// speedup vs baseline: 2.3413x; 1.4575x over previous
#include <cuda_runtime.h>

#define Bg 128
#define Ng 2048
#define Dd 256
#define Hh 16
#define Kk 32
#define Rr 16
#define BN (Bg*Ng)
#define NCHUNK 8
#define CHUNK 256

// scratch (static device arrays; no allocation)
__device__ unsigned g_pooled_enc[Bg*Dd];
__device__ float    g_keys [BN*Kk];     // [B,N,K]
__device__ float    g_evals[BN*Rr];     // [B,N,R]
__device__ float    g_q    [Bg*2*Hh*Kk];
__device__ float    g_embed[Bg*2*Hh*Rr];
__device__ float    g_part [Bg*NCHUNK*32*18];

__device__ __forceinline__ unsigned encf(float f) {
    unsigned u = __float_as_uint(f);
    return (u & 0x80000000u) ? ~u : (u | 0x80000000u);
}
__device__ __forceinline__ float decf(unsigned u) {
    u = (u & 0x80000000u) ? (u & 0x7FFFFFFFu) : ~u;
    return __uint_as_float(u);
}

__global__ void k_init() {
    g_pooled_enc[blockIdx.x * 256 + threadIdx.x] = 0u;
}

// ======================= baseline-ISA tensor helpers =======================
__device__ __forceinline__ unsigned smem_u32(const void* p) {
    unsigned a;
    asm("{ .reg .u64 t; cvta.to.shared.u64 t, %1; cvt.u32.u64 %0, t; }" : "=r"(a) : "l"(p));
    return a;
}
// pack two f32 into bf16x2 (elem0 -> low 16 bits)
#define CVT_BF2(r, lo, hi) asm("cvt.rn.satfinite.bf16x2.f32 %0, %1, %2;" : "=r"(r) : "f"(hi), "f"(lo))

__device__ __forceinline__ void ldm_x4(unsigned* a, unsigned addr) {
    asm volatile("ldmatrix.sync.aligned.m8n8.x4.shared.b16 {%0,%1,%2,%3}, [%4];"
                 : "=r"(a[0]), "=r"(a[1]), "=r"(a[2]), "=r"(a[3]) : "r"(addr));
}
__device__ __forceinline__ void mma_bf16(float* d, const unsigned* a, const unsigned* b) {
    asm volatile(
        "mma.sync.aligned.m16n8k16.row.col.f32.bf16.bf16.f32 "
        "{%0,%1,%2,%3}, {%4,%5,%6,%7}, {%8,%9}, {%0,%1,%2,%3};"
        : "+f"(d[0]), "+f"(d[1]), "+f"(d[2]), "+f"(d[3])
        : "r"(a[0]), "r"(a[1]), "r"(a[2]), "r"(a[3]), "r"(b[0]), "r"(b[1]));
}

// ---------------------------------------------------------------------------
// K2: persistent bf16-split3 GEMM via mma.sync: keys|e = x @ [Wk;We]^T (+max)
// D = Ah*Bh + Ah*Bl + Al*Bh. N = 48 = 6 n-tiles of 8. K = 256 = 16 k-steps.
// ---------------------------------------------------------------------------
#define ASTRIDE_B 528                      // 264 bf16 per row (pad for ldmatrix)
#define SM_MB   0                          // float[1024] col maxima
#define SM_BF   4096                       // B frags: [2][16][6][32][2] u32 = 49152B
#define SM_AH   (SM_BF + 49152)            // [128][264] bf16 = 67584B
#define SM_AL   (SM_AH + 67584)
#define SMEM_GEMM (SM_AL + 67584)          // 188416 bytes

__global__ void __launch_bounds__(256, 1)
k_gemm(const float* __restrict__ inp, const float* __restrict__ Wk,
       const float* __restrict__ We) {
    extern __shared__ char smem[];
    const unsigned sb = smem_u32(smem);
    const int t = threadIdx.x, w = t >> 5, lane = t & 31;
    const int gid = lane >> 2, tig = lane & 3;

    // ---- one-time: build split-bf16 B fragments in smem ----
    // idx -> (s, ks, nt, lane2): value pair for fragment reg b0/b1
    for (int idx = t; idx < 2 * 16 * 6 * 32; idx += 256) {
        const int l2 = idx & 31;
        const int nt = (idx >> 5) % 6;
        const int ks = (idx >> 5) / 6 % 16;
        const int s  = idx / (32 * 6 * 16);
        const int n  = nt * 8 + (l2 >> 2);
        const int k0 = ks * 16 + (l2 & 3) * 2;
        const float* wrow = (n < 32) ? (Wk + (size_t)n * 256) : (We + (size_t)(n - 32) * 256);
        float v0 = wrow[k0], v1 = wrow[k0 + 1], v2 = wrow[k0 + 8], v3 = wrow[k0 + 9];
        unsigned p0, p1;
        if (s == 0) {
            CVT_BF2(p0, v0, v1); CVT_BF2(p1, v2, v3);
        } else {
            unsigned h0, h1;
            CVT_BF2(h0, v0, v1); CVT_BF2(h1, v2, v3);
            const float e0 = v0 - __uint_as_float(h0 << 16);
            const float e1 = v1 - __uint_as_float(h0 & 0xFFFF0000u);
            const float e2 = v2 - __uint_as_float(h1 << 16);
            const float e3 = v3 - __uint_as_float(h1 & 0xFFFF0000u);
            CVT_BF2(p0, e0, e1); CVT_BF2(p1, e2, e3);
        }
        asm volatile("st.shared.v2.b32 [%0], {%1,%2};"
                     :: "r"(sb + SM_BF + idx * 8), "r"(p0), "r"(p1) : "memory");
    }

    const int c4 = t & 63;        // float4 column 0..63
    const int rg = t >> 6;        // row group of 32
    // ldmatrix lane address components (row = w*16 + (lane&15), half = lane>>4)
    const unsigned lm_off = (unsigned)((w * 16 + (lane & 15)) * ASTRIDE_B + ((lane >> 4) << 4));

    for (int tt = blockIdx.x; tt < BN / 128; tt += gridDim.x) {
        const int r0 = tt * 128, b = tt >> 4;

        // ---- load 128x256 f32 tile, split-convert to bf16, track col max ----
        float m0 = -3.4e38f, m1 = m0, m2 = m0, m3 = m0;
#pragma unroll 8
        for (int i = 0; i < 32; i++) {
            const int r = rg * 32 + i;
            const float4 v = ((const float4*)(inp + (size_t)(r0 + r) * 256))[c4];
            m0 = fmaxf(m0, v.x); m1 = fmaxf(m1, v.y);
            m2 = fmaxf(m2, v.z); m3 = fmaxf(m3, v.w);
            unsigned h01, h23, l01, l23;
            CVT_BF2(h01, v.x, v.y); CVT_BF2(h23, v.z, v.w);
            const float e0 = v.x - __uint_as_float(h01 << 16);
            const float e1 = v.y - __uint_as_float(h01 & 0xFFFF0000u);
            const float e2 = v.z - __uint_as_float(h23 << 16);
            const float e3 = v.w - __uint_as_float(h23 & 0xFFFF0000u);
            CVT_BF2(l01, e0, e1); CVT_BF2(l23, e2, e3);
            const unsigned off = (unsigned)(r * ASTRIDE_B + c4 * 8);
            asm volatile("st.shared.v2.b32 [%0], {%1,%2};" :: "r"(sb + SM_AH + off), "r"(h01), "r"(h23) : "memory");
            asm volatile("st.shared.v2.b32 [%0], {%1,%2};" :: "r"(sb + SM_AL + off), "r"(l01), "r"(l23) : "memory");
        }
        {
            float* Mb = (float*)(smem + SM_MB);
            Mb[rg * 256 + c4 * 4 + 0] = m0;
            Mb[rg * 256 + c4 * 4 + 1] = m1;
            Mb[rg * 256 + c4 * 4 + 2] = m2;
            Mb[rg * 256 + c4 * 4 + 3] = m3;
        }
        __syncthreads();

        {   // per-column max -> global pooled
            const float* Mb = (const float*)(smem + SM_MB);
            const float m = fmaxf(fmaxf(Mb[t], Mb[256 + t]), fmaxf(Mb[512 + t], Mb[768 + t]));
            atomicMax(&g_pooled_enc[b * 256 + t], encf(m));
        }

        // ---- mainloop: 16 k-steps x (AhBh + AhBl + AlBh) over 6 n-tiles ----
        float d[6][4];
#pragma unroll
        for (int nt = 0; nt < 6; nt++)
#pragma unroll
            for (int q = 0; q < 4; q++) d[nt][q] = 0.f;

#pragma unroll 4
        for (int ks = 0; ks < 16; ks++) {
            unsigned ah[4], al[4];
            ldm_x4(ah, sb + SM_AH + lm_off + ks * 32);
            ldm_x4(al, sb + SM_AL + lm_off + ks * 32);
            const unsigned bbase = sb + SM_BF + ((ks * 6) * 32 + lane) * 8;
#pragma unroll
            for (int nt = 0; nt < 6; nt++) {
                unsigned bh[2], bl[2];
                asm volatile("ld.shared.v2.b32 {%0,%1}, [%2];"
                             : "=r"(bh[0]), "=r"(bh[1]) : "r"(bbase + nt * 256));
                asm volatile("ld.shared.v2.b32 {%0,%1}, [%2];"
                             : "=r"(bl[0]), "=r"(bl[1]) : "r"(bbase + nt * 256 + 16 * 6 * 256));
                mma_bf16(d[nt], ah, bh);
                mma_bf16(d[nt], ah, bl);
                mma_bf16(d[nt], al, bh);
            }
        }

        // ---- epilogue: D fragments -> g_keys / g_evals ----
        {
            const int row0 = r0 + w * 16 + gid;
#pragma unroll
            for (int nt = 0; nt < 6; nt++) {
                const int c = nt * 8 + tig * 2;
                if (nt < 4) {
                    *(float2*)(g_keys + (size_t)row0 * 32 + c)       = make_float2(d[nt][0], d[nt][1]);
                    *(float2*)(g_keys + (size_t)(row0 + 8) * 32 + c) = make_float2(d[nt][2], d[nt][3]);
                } else {
                    *(float2*)(g_evals + (size_t)row0 * 16 + (c - 32))       = make_float2(d[nt][0], d[nt][1]);
                    *(float2*)(g_evals + (size_t)(row0 + 8) * 16 + (c - 32)) = make_float2(d[nt][2], d[nt][3]);
                }
            }
        }
        __syncthreads();   // all warps done reading A before next tile's stores
    }
}

// ---------------------------------------------------------------------------
// K3: q[b, vh*32 + k] = pooled[b] . Wq_v[h*32+k]
// ---------------------------------------------------------------------------
__global__ void k_q(const float* __restrict__ Wq0, const float* __restrict__ Wq1) {
    __shared__ float ps[256];
    const int b = blockIdx.x, t = threadIdx.x;
    ps[t] = decf(g_pooled_enc[b * 256 + t]);
    __syncthreads();
#pragma unroll
    for (int g = 0; g < 4; g++) {
        const int o = g * 256 + t;
        const float* wrow = (o < 512) ? (Wq0 + (size_t)o * 256)
                                      : (Wq1 + (size_t)(o - 512) * 256);
        const float4* w4 = (const float4*)wrow;
        float acc = 0.f;
#pragma unroll 8
        for (int k4 = 0; k4 < 64; k4++) {
            const float4 w = w4[k4];
            acc = fmaf(ps[4*k4+0], w.x, acc);
            acc = fmaf(ps[4*k4+1], w.y, acc);
            acc = fmaf(ps[4*k4+2], w.z, acc);
            acc = fmaf(ps[4*k4+3], w.w, acc);
        }
        g_q[b * 1024 + o] = acc;
    }
}

// ---------------------------------------------------------------------------
// K4a: split-softmax partials (unchanged)
// ---------------------------------------------------------------------------
#define KS_STRIDE 36
#define ES_STRIDE 20
#define SMEM_ATTN ((CHUNK*KS_STRIDE + CHUNK*ES_STRIDE + 32*32) * 4)

__global__ void __launch_bounds__(256, 2)
k_attn_part() {
    extern __shared__ float sm[];
    float* ks = sm;
    float* es = ks + CHUNK * KS_STRIDE;
    float* qs = es + CHUNK * ES_STRIDE;

    const int b = blockIdx.x, ch = blockIdx.y, t = threadIdx.x;
    const int n0 = ch * CHUNK;
    const float* keysb = g_keys  + ((size_t)b * Ng + n0) * 32;
    const float* eb    = g_evals + ((size_t)b * Ng + n0) * 16;

    for (int idx = t; idx < CHUNK * 8; idx += 256) {
        const int n = idx >> 3, k4 = idx & 7;
        ((float4*)(ks + n * KS_STRIDE))[k4] = ((const float4*)keysb)[idx];
    }
    for (int idx = t; idx < CHUNK * 4; idx += 256) {
        const int n = idx >> 2, r4 = idx & 3;
        ((float4*)(es + n * ES_STRIDE))[r4] = ((const float4*)eb)[idx];
    }
    for (int idx = t; idx < 1024; idx += 256)
        qs[idx] = g_q[b * 1024 + idx];
    __syncthreads();

    const int g  = t & 31;
    const int vq = t >> 5;

    float l[4][8];
#pragma unroll
    for (int vv = 0; vv < 4; vv++)
#pragma unroll
        for (int i = 0; i < 8; i++) l[vv][i] = 0.f;

#pragma unroll
    for (int k4 = 0; k4 < 8; k4++) {
        float4 q4[4];
#pragma unroll
        for (int vv = 0; vv < 4; vv++)
            q4[vv] = ((const float4*)(qs + (vq * 4 + vv) * 32))[k4];
#pragma unroll
        for (int i = 0; i < 8; i++) {
            const float4 kv = ((const float4*)(ks + (g + 32 * i) * KS_STRIDE))[k4];
#pragma unroll
            for (int vv = 0; vv < 4; vv++) {
                l[vv][i] = fmaf(q4[vv].x, kv.x, l[vv][i]);
                l[vv][i] = fmaf(q4[vv].y, kv.y, l[vv][i]);
                l[vv][i] = fmaf(q4[vv].z, kv.z, l[vv][i]);
                l[vv][i] = fmaf(q4[vv].w, kv.w, l[vv][i]);
            }
        }
    }

    float m[4], s[4];
#pragma unroll
    for (int vv = 0; vv < 4; vv++) {
        float mx = l[vv][0];
#pragma unroll
        for (int i = 1; i < 8; i++) mx = fmaxf(mx, l[vv][i]);
#pragma unroll
        for (int o = 16; o; o >>= 1) mx = fmaxf(mx, __shfl_xor_sync(0xffffffffu, mx, o));
        m[vv] = mx;
        float ss = 0.f;
#pragma unroll
        for (int i = 0; i < 8; i++) {
            const float e = __expf(l[vv][i] - mx);
            l[vv][i] = e;
            ss += e;
        }
#pragma unroll
        for (int o = 16; o; o >>= 1) ss += __shfl_xor_sync(0xffffffffu, ss, o);
        s[vv] = ss;
    }

    float acc[4][16];
#pragma unroll
    for (int vv = 0; vv < 4; vv++)
#pragma unroll
        for (int r = 0; r < 16; r++) acc[vv][r] = 0.f;

#pragma unroll
    for (int i = 0; i < 8; i++) {
        const float4* erow = (const float4*)(es + (g + 32 * i) * ES_STRIDE);
        float4 e0 = erow[0], e1 = erow[1], e2 = erow[2], e3 = erow[3];
#pragma unroll
        for (int vv = 0; vv < 4; vv++) {
            const float ev = l[vv][i];
            acc[vv][0]  = fmaf(ev, e0.x, acc[vv][0]);
            acc[vv][1]  = fmaf(ev, e0.y, acc[vv][1]);
            acc[vv][2]  = fmaf(ev, e0.z, acc[vv][2]);
            acc[vv][3]  = fmaf(ev, e0.w, acc[vv][3]);
            acc[vv][4]  = fmaf(ev, e1.x, acc[vv][4]);
            acc[vv][5]  = fmaf(ev, e1.y, acc[vv][5]);
            acc[vv][6]  = fmaf(ev, e1.z, acc[vv][6]);
            acc[vv][7]  = fmaf(ev, e1.w, acc[vv][7]);
            acc[vv][8]  = fmaf(ev, e2.x, acc[vv][8]);
            acc[vv][9]  = fmaf(ev, e2.y, acc[vv][9]);
            acc[vv][10] = fmaf(ev, e2.z, acc[vv][10]);
            acc[vv][11] = fmaf(ev, e2.w, acc[vv][11]);
            acc[vv][12] = fmaf(ev, e3.x, acc[vv][12]);
            acc[vv][13] = fmaf(ev, e3.y, acc[vv][13]);
            acc[vv][14] = fmaf(ev, e3.z, acc[vv][14]);
            acc[vv][15] = fmaf(ev, e3.w, acc[vv][15]);
        }
    }

#pragma unroll
    for (int vv = 0; vv < 4; vv++)
#pragma unroll
        for (int r = 0; r < 16; r++) {
            float a = acc[vv][r];
#pragma unroll
            for (int o = 16; o; o >>= 1) a += __shfl_xor_sync(0xffffffffu, a, o);
            acc[vv][r] = a;
        }

    if (g == 0) {
        float* p = g_part + (((size_t)(b * NCHUNK + ch) * 32) + vq * 4) * 18;
#pragma unroll
        for (int vv = 0; vv < 4; vv++) {
            p[vv * 18 + 0] = m[vv];
            p[vv * 18 + 1] = s[vv];
#pragma unroll
            for (int r = 0; r < 16; r++) p[vv * 18 + 2 + r] = acc[vv][r];
        }
    }
}

__global__ void k_attn_red() {
    const int b = blockIdx.x, vh = threadIdx.x;
    const float* base = g_part + (size_t)b * NCHUNK * 32 * 18 + vh * 18;
    float M = __int_as_float(0xff800000);
#pragma unroll
    for (int c = 0; c < NCHUNK; c++) M = fmaxf(M, base[c * 32 * 18]);
    float S = 0.f, acc[16];
#pragma unroll
    for (int r = 0; r < 16; r++) acc[r] = 0.f;
#pragma unroll
    for (int c = 0; c < NCHUNK; c++) {
        const float* p = base + c * 32 * 18;
        const float w = __expf(p[0] - M);
        S = fmaf(p[1], w, S);
#pragma unroll
        for (int r = 0; r < 16; r++) acc[r] = fmaf(p[2 + r], w, acc[r]);
    }
    const float inv = 1.f / S;
#pragma unroll
    for (int r = 0; r < 16; r++)
        g_embed[b * 512 + vh * 16 + r] = acc[r] * inv;
}

__global__ void k_out(const float* __restrict__ Wout, const float* __restrict__ bout,
                      float* __restrict__ out) {
    __shared__ float dx[256];
    const int b = blockIdx.x, t = threadIdx.x;
    dx[t] = g_embed[b * 512 + t] - g_embed[b * 512 + 256 + t];
    __syncthreads();
    float acc = bout[t];
    const float4* w4 = (const float4*)(Wout + (size_t)t * 256);
#pragma unroll 8
    for (int k4 = 0; k4 < 64; k4++) {
        const float4 w = w4[k4];
        acc = fmaf(dx[4*k4+0], w.x, acc);
        acc = fmaf(dx[4*k4+1], w.y, acc);
        acc = fmaf(dx[4*k4+2], w.z, acc);
        acc = fmaf(dx[4*k4+3], w.w, acc);
    }
    out[b * 256 + t] = acc >= 0.f ? acc : 0.01f * acc;
}

extern "C" void kernel_launch(void* const* d_in, const int* in_sizes, int n_in,
                              void* d_out, int out_size) {
    const float* inp  = (const float*)d_in[0];
    const float* Wk   = (const float*)d_in[2];
    const float* Wq0  = (const float*)d_in[3];
    const float* Wq1  = (const float*)d_in[4];
    const float* We   = (const float*)d_in[5];
    const float* Wout = (const float*)d_in[6];
    const float* bout = (const float*)d_in[7];
    float* out = (float*)d_out;

    cudaFuncSetAttribute(k_gemm, cudaFuncAttributeMaxDynamicSharedMemorySize, SMEM_GEMM);
    cudaFuncSetAttribute(k_attn_part, cudaFuncAttributeMaxDynamicSharedMemorySize, SMEM_ATTN);

    k_init<<<128, 256>>>();
    k_gemm<<<148, 256, SMEM_GEMM>>>(inp, Wk, We);
    k_q<<<Bg, 256>>>(Wq0, Wq1);
    k_attn_part<<<dim3(Bg, NCHUNK), 256, SMEM_ATTN>>>();
    k_attn_red<<<Bg, 32>>>();
    k_out<<<Bg, 256>>>(Wout, bout, out);
}

// round 6
// speedup vs baseline: 2.4007x; 1.0254x over previous
#include <cuda_runtime.h>

#define Bg 128
#define Ng 2048
#define Dd 256
#define Hh 16
#define Kk 32
#define Rr 16
#define BN (Bg*Ng)
#define NCHUNK 8
#define CHUNK 256

// scratch (static device arrays; no allocation)
__device__ unsigned g_pooled_enc[Bg*Dd];
__device__ float    g_keys [BN*Kk];     // [B,N,K]
__device__ float    g_evals[BN*Rr];     // [B,N,R]
__device__ float    g_q    [Bg*2*Hh*Kk];
__device__ float    g_embed[Bg*2*Hh*Rr];
__device__ float    g_part [Bg*NCHUNK*32*18];

__device__ __forceinline__ unsigned encf(float f) {
    unsigned u = __float_as_uint(f);
    return (u & 0x80000000u) ? ~u : (u | 0x80000000u);
}
__device__ __forceinline__ float decf(unsigned u) {
    u = (u & 0x80000000u) ? (u & 0x7FFFFFFFu) : ~u;
    return __uint_as_float(u);
}

__global__ void k_init() {
    g_pooled_enc[blockIdx.x * 256 + threadIdx.x] = 0u;
}

// ======================= baseline-ISA tensor helpers =======================
__device__ __forceinline__ unsigned smem_u32(const void* p) {
    unsigned a;
    asm("{ .reg .u64 t; cvta.to.shared.u64 t, %1; cvt.u32.u64 %0, t; }" : "=r"(a) : "l"(p));
    return a;
}
#define CVT_BF2(r, lo, hi) asm("cvt.rn.satfinite.bf16x2.f32 %0, %1, %2;" : "=r"(r) : "f"(hi), "f"(lo))

__device__ __forceinline__ void ldm_x4(unsigned* a, unsigned addr) {
    asm volatile("ldmatrix.sync.aligned.m8n8.x4.shared.b16 {%0,%1,%2,%3}, [%4];"
                 : "=r"(a[0]), "=r"(a[1]), "=r"(a[2]), "=r"(a[3]) : "r"(addr));
}
__device__ __forceinline__ void mma_bf16(float* d, const unsigned* a, const unsigned* b) {
    asm volatile(
        "mma.sync.aligned.m16n8k16.row.col.f32.bf16.bf16.f32 "
        "{%0,%1,%2,%3}, {%4,%5,%6,%7}, {%8,%9}, {%0,%1,%2,%3};"
        : "+f"(d[0]), "+f"(d[1]), "+f"(d[2]), "+f"(d[3])
        : "r"(a[0]), "r"(a[1]), "r"(a[2]), "r"(a[3]), "r"(b[0]), "r"(b[1]));
}

// ---------------------------------------------------------------------------
// K2: persistent bf16-split3 GEMM via mma.sync: keys|e = x @ [Wk;We]^T (+max)
// ---------------------------------------------------------------------------
#define ASTRIDE_B 528                      // A row pitch (bytes)
#define BLANE_B   144                      // B per-(s,nt,lane) pitch: 16ks x 8B + pad
#define SM_MB   0                          // float[1024] col maxima
#define SM_BF   4096                       // B frags: 12*32*144 = 55296 B
#define SM_AH   (SM_BF + 55296)            // [128][264] bf16 = 67584B
#define SM_AL   (SM_AH + 67584)
#define SMEM_GEMM (SM_AL + 67584)          // 194560 bytes

__global__ void __launch_bounds__(256, 1)
k_gemm(const float* __restrict__ inp, const float* __restrict__ Wk,
       const float* __restrict__ We) {
    extern __shared__ char smem[];
    const unsigned sb = smem_u32(smem);
    const int t = threadIdx.x, w = t >> 5, lane = t & 31;
    const int gid = lane >> 2, tig = lane & 3;

    // ---- one-time: build split-bf16 B fragments in smem ----
    for (int idx = t; idx < 2 * 16 * 6 * 32; idx += 256) {
        const int l2 = idx & 31;
        const int nt = (idx >> 5) % 6;
        const int ks = (idx >> 5) / 6 % 16;
        const int s  = idx / (32 * 6 * 16);
        const int n  = nt * 8 + (l2 >> 2);
        const int k0 = ks * 16 + (l2 & 3) * 2;
        const float* wrow = (n < 32) ? (Wk + (size_t)n * 256) : (We + (size_t)(n - 32) * 256);
        float v0 = wrow[k0], v1 = wrow[k0 + 1], v2 = wrow[k0 + 8], v3 = wrow[k0 + 9];
        unsigned p0, p1;
        if (s == 0) {
            CVT_BF2(p0, v0, v1); CVT_BF2(p1, v2, v3);
        } else {
            unsigned h0, h1;
            CVT_BF2(h0, v0, v1); CVT_BF2(h1, v2, v3);
            const float e0 = v0 - __uint_as_float(h0 << 16);
            const float e1 = v1 - __uint_as_float(h0 & 0xFFFF0000u);
            const float e2 = v2 - __uint_as_float(h1 << 16);
            const float e3 = v3 - __uint_as_float(h1 & 0xFFFF0000u);
            CVT_BF2(p0, e0, e1); CVT_BF2(p1, e2, e3);
        }
        const unsigned addr = sb + SM_BF + (unsigned)(((s * 6 + nt) * 32 + l2) * BLANE_B + ks * 8);
        asm volatile("st.shared.v2.b32 [%0], {%1,%2};" :: "r"(addr), "r"(p0), "r"(p1) : "memory");
    }

    const int c4 = t & 63;
    const int rg = t >> 6;
    const unsigned lm_off = (unsigned)((w * 16 + (lane & 15)) * ASTRIDE_B + ((lane >> 4) << 4));

    for (int tt = blockIdx.x; tt < BN / 128; tt += gridDim.x) {
        const int r0 = tt * 128, b = tt >> 4;

        // prefetch next tile into L2
        {
            const int tn = tt + gridDim.x;
            if (tn < BN / 128) {
                const char* nb = (const char*)(inp + (size_t)tn * 128 * 256);
#pragma unroll
                for (int j = 0; j < 4; j++)
                    asm volatile("prefetch.global.L2 [%0];" :: "l"(nb + (t + j * 256) * 128));
            }
        }

        // ---- load 128x256 f32 tile, split-convert to bf16, track col max ----
        float m0 = -3.4e38f, m1 = m0, m2 = m0, m3 = m0;
#pragma unroll 8
        for (int i = 0; i < 32; i++) {
            const int r = rg * 32 + i;
            const float4 v = ((const float4*)(inp + (size_t)(r0 + r) * 256))[c4];
            m0 = fmaxf(m0, v.x); m1 = fmaxf(m1, v.y);
            m2 = fmaxf(m2, v.z); m3 = fmaxf(m3, v.w);
            unsigned h01, h23, l01, l23;
            CVT_BF2(h01, v.x, v.y); CVT_BF2(h23, v.z, v.w);
            const float e0 = v.x - __uint_as_float(h01 << 16);
            const float e1 = v.y - __uint_as_float(h01 & 0xFFFF0000u);
            const float e2 = v.z - __uint_as_float(h23 << 16);
            const float e3 = v.w - __uint_as_float(h23 & 0xFFFF0000u);
            CVT_BF2(l01, e0, e1); CVT_BF2(l23, e2, e3);
            const unsigned off = (unsigned)(r * ASTRIDE_B + c4 * 8);
            asm volatile("st.shared.v2.b32 [%0], {%1,%2};" :: "r"(sb + SM_AH + off), "r"(h01), "r"(h23) : "memory");
            asm volatile("st.shared.v2.b32 [%0], {%1,%2};" :: "r"(sb + SM_AL + off), "r"(l01), "r"(l23) : "memory");
        }
        {
            float* Mb = (float*)(smem + SM_MB);
            Mb[rg * 256 + c4 * 4 + 0] = m0;
            Mb[rg * 256 + c4 * 4 + 1] = m1;
            Mb[rg * 256 + c4 * 4 + 2] = m2;
            Mb[rg * 256 + c4 * 4 + 3] = m3;
        }
        __syncthreads();

        {
            const float* Mb = (const float*)(smem + SM_MB);
            const float m = fmaxf(fmaxf(Mb[t], Mb[256 + t]), fmaxf(Mb[512 + t], Mb[768 + t]));
            atomicMax(&g_pooled_enc[b * 256 + t], encf(m));
        }

        // ---- mainloop: 2 k-steps per iter, lds.128 B-frags ----
        float d[6][4];
#pragma unroll
        for (int nt = 0; nt < 6; nt++)
#pragma unroll
            for (int q = 0; q < 4; q++) d[nt][q] = 0.f;

#pragma unroll 2
        for (int ks = 0; ks < 16; ks += 2) {
            unsigned ah0[4], al0[4], ah1[4], al1[4];
            ldm_x4(ah0, sb + SM_AH + lm_off + ks * 32);
            ldm_x4(al0, sb + SM_AL + lm_off + ks * 32);
            ldm_x4(ah1, sb + SM_AH + lm_off + ks * 32 + 32);
            ldm_x4(al1, sb + SM_AL + lm_off + ks * 32 + 32);
            const unsigned bb = sb + SM_BF + lane * BLANE_B + ks * 8;
#pragma unroll
            for (int nt = 0; nt < 6; nt++) {
                unsigned bh[4], bl[4];
                asm volatile("ld.shared.v4.b32 {%0,%1,%2,%3}, [%4];"
                             : "=r"(bh[0]), "=r"(bh[1]), "=r"(bh[2]), "=r"(bh[3])
                             : "r"(bb + nt * 32 * BLANE_B));
                asm volatile("ld.shared.v4.b32 {%0,%1,%2,%3}, [%4];"
                             : "=r"(bl[0]), "=r"(bl[1]), "=r"(bl[2]), "=r"(bl[3])
                             : "r"(bb + (6 + nt) * 32 * BLANE_B));
                mma_bf16(d[nt], ah0, bh);
                mma_bf16(d[nt], ah0, bl);
                mma_bf16(d[nt], al0, bh);
                mma_bf16(d[nt], ah1, bh + 2);
                mma_bf16(d[nt], ah1, bl + 2);
                mma_bf16(d[nt], al1, bh + 2);
            }
        }

        // ---- epilogue: D fragments -> g_keys / g_evals ----
        {
            const int row0 = r0 + w * 16 + gid;
#pragma unroll
            for (int nt = 0; nt < 6; nt++) {
                const int c = nt * 8 + tig * 2;
                if (nt < 4) {
                    *(float2*)(g_keys + (size_t)row0 * 32 + c)       = make_float2(d[nt][0], d[nt][1]);
                    *(float2*)(g_keys + (size_t)(row0 + 8) * 32 + c) = make_float2(d[nt][2], d[nt][3]);
                } else {
                    *(float2*)(g_evals + (size_t)row0 * 16 + (c - 32))       = make_float2(d[nt][0], d[nt][1]);
                    *(float2*)(g_evals + (size_t)(row0 + 8) * 16 + (c - 32)) = make_float2(d[nt][2], d[nt][3]);
                }
            }
        }
        __syncthreads();
    }
}

// ---------------------------------------------------------------------------
// K3: q = pooled @ [Wq0;Wq1]^T  — weight-stationary: 128 blocks x 8 cols
// ---------------------------------------------------------------------------
#define QW_STRIDE 268
__global__ void __launch_bounds__(256)
k_q(const float* __restrict__ Wq0, const float* __restrict__ Wq1) {
    __shared__ float Ws[8 * QW_STRIDE];
    const int t = threadIdx.x;
    const int c0 = blockIdx.x * 8;
    for (int idx = t; idx < 8 * 256; idx += 256) {
        const int row = idx >> 8, k = idx & 255;
        const int o = c0 + row;
        Ws[row * QW_STRIDE + k] = (o < 512) ? Wq0[(size_t)o * 256 + k]
                                            : Wq1[(size_t)(o - 512) * 256 + k];
    }
    __syncthreads();
    const int col = t & 7, gs = t >> 3;
    const float4* w4 = (const float4*)(Ws + col * QW_STRIDE);
#pragma unroll
    for (int kk = 0; kk < 4; kk++) {
        const int g = gs + 32 * kk;
        const uint4* p4 = (const uint4*)(g_pooled_enc + g * 256);
        float acc = 0.f;
#pragma unroll 8
        for (int j = 0; j < 64; j++) {
            const uint4 e = p4[j];
            const float4 w = w4[j];
            acc = fmaf(decf(e.x), w.x, acc);
            acc = fmaf(decf(e.y), w.y, acc);
            acc = fmaf(decf(e.z), w.z, acc);
            acc = fmaf(decf(e.w), w.w, acc);
        }
        g_q[g * 1024 + c0 + col] = acc;
    }
}

// ---------------------------------------------------------------------------
// K4a: split-softmax partials. grid (128, 8, 2): 16 vh per block, 2 per warp.
// ---------------------------------------------------------------------------
#define KS_STRIDE 36
#define ES_STRIDE 20
#define SMEM_ATTN ((CHUNK*KS_STRIDE + CHUNK*ES_STRIDE + 16*32) * 4)

__global__ void __launch_bounds__(256, 3)
k_attn_part() {
    extern __shared__ float sm[];
    float* ks = sm;
    float* es = ks + CHUNK * KS_STRIDE;
    float* qs = es + CHUNK * ES_STRIDE;

    const int b = blockIdx.x, ch = blockIdx.y, t = threadIdx.x;
    const int vh0 = blockIdx.z * 16;
    const int n0 = ch * CHUNK;
    const float* keysb = g_keys  + ((size_t)b * Ng + n0) * 32;
    const float* eb    = g_evals + ((size_t)b * Ng + n0) * 16;

    for (int idx = t; idx < CHUNK * 8; idx += 256) {
        const int n = idx >> 3, k4 = idx & 7;
        ((float4*)(ks + n * KS_STRIDE))[k4] = ((const float4*)keysb)[idx];
    }
    for (int idx = t; idx < CHUNK * 4; idx += 256) {
        const int n = idx >> 2, r4 = idx & 3;
        ((float4*)(es + n * ES_STRIDE))[r4] = ((const float4*)eb)[idx];
    }
    for (int idx = t; idx < 512; idx += 256)
        qs[idx] = g_q[b * 1024 + vh0 * 32 + idx];
    __syncthreads();

    const int g  = t & 31;
    const int vq = t >> 5;

    float l[2][8];
#pragma unroll
    for (int vv = 0; vv < 2; vv++)
#pragma unroll
        for (int i = 0; i < 8; i++) l[vv][i] = 0.f;

#pragma unroll
    for (int k4 = 0; k4 < 8; k4++) {
        float4 q4[2];
#pragma unroll
        for (int vv = 0; vv < 2; vv++)
            q4[vv] = ((const float4*)(qs + (vq * 2 + vv) * 32))[k4];
#pragma unroll
        for (int i = 0; i < 8; i++) {
            const float4 kv = ((const float4*)(ks + (g + 32 * i) * KS_STRIDE))[k4];
#pragma unroll
            for (int vv = 0; vv < 2; vv++) {
                l[vv][i] = fmaf(q4[vv].x, kv.x, l[vv][i]);
                l[vv][i] = fmaf(q4[vv].y, kv.y, l[vv][i]);
                l[vv][i] = fmaf(q4[vv].z, kv.z, l[vv][i]);
                l[vv][i] = fmaf(q4[vv].w, kv.w, l[vv][i]);
            }
        }
    }

    float m[2], s[2];
#pragma unroll
    for (int vv = 0; vv < 2; vv++) {
        float mx = l[vv][0];
#pragma unroll
        for (int i = 1; i < 8; i++) mx = fmaxf(mx, l[vv][i]);
#pragma unroll
        for (int o = 16; o; o >>= 1) mx = fmaxf(mx, __shfl_xor_sync(0xffffffffu, mx, o));
        m[vv] = mx;
        float ss = 0.f;
#pragma unroll
        for (int i = 0; i < 8; i++) {
            const float e = __expf(l[vv][i] - mx);
            l[vv][i] = e;
            ss += e;
        }
#pragma unroll
        for (int o = 16; o; o >>= 1) ss += __shfl_xor_sync(0xffffffffu, ss, o);
        s[vv] = ss;
    }

    float acc[2][16];
#pragma unroll
    for (int vv = 0; vv < 2; vv++)
#pragma unroll
        for (int r = 0; r < 16; r++) acc[vv][r] = 0.f;

#pragma unroll
    for (int i = 0; i < 8; i++) {
        const float4* erow = (const float4*)(es + (g + 32 * i) * ES_STRIDE);
        float4 e0 = erow[0], e1 = erow[1], e2 = erow[2], e3 = erow[3];
#pragma unroll
        for (int vv = 0; vv < 2; vv++) {
            const float ev = l[vv][i];
            acc[vv][0]  = fmaf(ev, e0.x, acc[vv][0]);
            acc[vv][1]  = fmaf(ev, e0.y, acc[vv][1]);
            acc[vv][2]  = fmaf(ev, e0.z, acc[vv][2]);
            acc[vv][3]  = fmaf(ev, e0.w, acc[vv][3]);
            acc[vv][4]  = fmaf(ev, e1.x, acc[vv][4]);
            acc[vv][5]  = fmaf(ev, e1.y, acc[vv][5]);
            acc[vv][6]  = fmaf(ev, e1.z, acc[vv][6]);
            acc[vv][7]  = fmaf(ev, e1.w, acc[vv][7]);
            acc[vv][8]  = fmaf(ev, e2.x, acc[vv][8]);
            acc[vv][9]  = fmaf(ev, e2.y, acc[vv][9]);
            acc[vv][10] = fmaf(ev, e2.z, acc[vv][10]);
            acc[vv][11] = fmaf(ev, e2.w, acc[vv][11]);
            acc[vv][12] = fmaf(ev, e3.x, acc[vv][12]);
            acc[vv][13] = fmaf(ev, e3.y, acc[vv][13]);
            acc[vv][14] = fmaf(ev, e3.z, acc[vv][14]);
            acc[vv][15] = fmaf(ev, e3.w, acc[vv][15]);
        }
    }

#pragma unroll
    for (int vv = 0; vv < 2; vv++)
#pragma unroll
        for (int r = 0; r < 16; r++) {
            float a = acc[vv][r];
#pragma unroll
            for (int o = 16; o; o >>= 1) a += __shfl_xor_sync(0xffffffffu, a, o);
            acc[vv][r] = a;
        }

    if (g == 0) {
        float* p = g_part + (((size_t)(b * NCHUNK + ch) * 32) + vh0 + vq * 2) * 18;
#pragma unroll
        for (int vv = 0; vv < 2; vv++) {
            p[vv * 18 + 0] = m[vv];
            p[vv * 18 + 1] = s[vv];
#pragma unroll
            for (int r = 0; r < 16; r++) p[vv * 18 + 2 + r] = acc[vv][r];
        }
    }
}

__global__ void k_attn_red() {
    const int b = blockIdx.x, vh = threadIdx.x;
    const float* base = g_part + (size_t)b * NCHUNK * 32 * 18 + vh * 18;
    float M = __int_as_float(0xff800000);
#pragma unroll
    for (int c = 0; c < NCHUNK; c++) M = fmaxf(M, base[c * 32 * 18]);
    float S = 0.f, acc[16];
#pragma unroll
    for (int r = 0; r < 16; r++) acc[r] = 0.f;
#pragma unroll
    for (int c = 0; c < NCHUNK; c++) {
        const float* p = base + c * 32 * 18;
        const float w = __expf(p[0] - M);
        S = fmaf(p[1], w, S);
#pragma unroll
        for (int r = 0; r < 16; r++) acc[r] = fmaf(p[2 + r], w, acc[r]);
    }
    const float inv = 1.f / S;
#pragma unroll
    for (int r = 0; r < 16; r++)
        g_embed[b * 512 + vh * 16 + r] = acc[r] * inv;
}

// ---------------------------------------------------------------------------
// K5: out = leaky((embed0-embed1) @ Wout^T + bout) — 32 blocks x 8 dims
// ---------------------------------------------------------------------------
__global__ void __launch_bounds__(256)
k_out(const float* __restrict__ Wout, const float* __restrict__ bout,
      float* __restrict__ out) {
    __shared__ float Ws[8 * QW_STRIDE];
    const int t = threadIdx.x;
    const int d0 = blockIdx.x * 8;
    for (int idx = t; idx < 8 * 256; idx += 256) {
        const int row = idx >> 8, k = idx & 255;
        Ws[row * QW_STRIDE + k] = Wout[(size_t)(d0 + row) * 256 + k];
    }
    __syncthreads();
    const int col = t & 7, gs = t >> 3;
    const int d = d0 + col;
    const float bv = bout[d];
    const float4* w4 = (const float4*)(Ws + col * QW_STRIDE);
#pragma unroll
    for (int kk = 0; kk < 4; kk++) {
        const int g = gs + 32 * kk;
        const float4* e0p = (const float4*)(g_embed + g * 512);
        const float4* e1p = (const float4*)(g_embed + g * 512 + 256);
        float acc = bv;
#pragma unroll 8
        for (int j = 0; j < 64; j++) {
            const float4 a = e0p[j], bq = e1p[j], w = w4[j];
            acc = fmaf(a.x - bq.x, w.x, acc);
            acc = fmaf(a.y - bq.y, w.y, acc);
            acc = fmaf(a.z - bq.z, w.z, acc);
            acc = fmaf(a.w - bq.w, w.w, acc);
        }
        out[g * 256 + d] = acc >= 0.f ? acc : 0.01f * acc;
    }
}

extern "C" void kernel_launch(void* const* d_in, const int* in_sizes, int n_in,
                              void* d_out, int out_size) {
    const float* inp  = (const float*)d_in[0];
    const float* Wk   = (const float*)d_in[2];
    const float* Wq0  = (const float*)d_in[3];
    const float* Wq1  = (const float*)d_in[4];
    const float* We   = (const float*)d_in[5];
    const float* Wout = (const float*)d_in[6];
    const float* bout = (const float*)d_in[7];
    float* out = (float*)d_out;

    cudaFuncSetAttribute(k_gemm, cudaFuncAttributeMaxDynamicSharedMemorySize, SMEM_GEMM);
    cudaFuncSetAttribute(k_attn_part, cudaFuncAttributeMaxDynamicSharedMemorySize, SMEM_ATTN);

    k_init<<<128, 256>>>();
    k_gemm<<<148, 256, SMEM_GEMM>>>(inp, Wk, We);
    k_q<<<128, 256>>>(Wq0, Wq1);
    k_attn_part<<<dim3(Bg, NCHUNK, 2), 256, SMEM_ATTN>>>();
    k_attn_red<<<Bg, 32>>>();
    k_out<<<32, 256>>>(Wout, bout, out);
}

// round 7
// speedup vs baseline: 2.5194x; 1.0495x over previous
#include <cuda_runtime.h>

#define Bg 128
#define Ng 2048
#define Dd 256
#define Hh 16
#define Kk 32
#define Rr 16
#define BN (Bg*Ng)
#define NT (BN/128)
#define NCHUNK 8
#define CHUNK 256

// scratch (static device arrays; no allocation)
__device__ unsigned g_pooled_enc[Bg*Dd];
__device__ float    g_keys [BN*Kk];     // [B,N,K]
__device__ float    g_evals[BN*Rr];     // [B,N,R]
__device__ float    g_q    [Bg*2*Hh*Kk];
__device__ float    g_embed[Bg*2*Hh*Rr];
__device__ float    g_part [Bg*NCHUNK*32*18];

__device__ __forceinline__ unsigned encf(float f) {
    unsigned u = __float_as_uint(f);
    return (u & 0x80000000u) ? ~u : (u | 0x80000000u);
}
__device__ __forceinline__ float decf(unsigned u) {
    u = (u & 0x80000000u) ? (u & 0x7FFFFFFFu) : ~u;
    return __uint_as_float(u);
}

__global__ void k_init() {
    g_pooled_enc[blockIdx.x * 256 + threadIdx.x] = 0u;
}

// ======================= baseline-ISA tensor helpers =======================
__device__ __forceinline__ unsigned smem_u32(const void* p) {
    unsigned a;
    asm("{ .reg .u64 t; cvta.to.shared.u64 t, %1; cvt.u32.u64 %0, t; }" : "=r"(a) : "l"(p));
    return a;
}
#define CVT_BF2(r, lo, hi) asm("cvt.rn.satfinite.bf16x2.f32 %0, %1, %2;" : "=r"(r) : "f"(hi), "f"(lo))

__device__ __forceinline__ void ldm_x4(unsigned* a, unsigned addr) {
    asm volatile("ldmatrix.sync.aligned.m8n8.x4.shared.b16 {%0,%1,%2,%3}, [%4];"
                 : "=r"(a[0]), "=r"(a[1]), "=r"(a[2]), "=r"(a[3]) : "r"(addr));
}
__device__ __forceinline__ void mma_bf16(float* d, const unsigned* a, const unsigned* b) {
    asm volatile(
        "mma.sync.aligned.m16n8k16.row.col.f32.bf16.bf16.f32 "
        "{%0,%1,%2,%3}, {%4,%5,%6,%7}, {%8,%9}, {%0,%1,%2,%3};"
        : "+f"(d[0]), "+f"(d[1]), "+f"(d[2]), "+f"(d[3])
        : "r"(a[0]), "r"(a[1]), "r"(a[2]), "r"(a[3]), "r"(b[0]), "r"(b[1]));
}

// ---------------------------------------------------------------------------
// K2: pipelined persistent bf16-split3 GEMM: keys|e = x @ [Wk;We]^T (+max)
// K split into 4 quarters of 64; two A staging buffers; per quarter:
// convert+store -> sync -> LDG next quarter -> MMA (covers DRAM latency).
// ---------------------------------------------------------------------------
#define BLANE_B  144
#define APITCH   144                        // 64 bf16 = 128 B + 16 pad
#define QBUF     (128*APITCH)               // 18432 B per split
#define SM_BF    1024                       // after Mb (256 u32)
#define SM_A     (SM_BF + 55296)            // 2 bufs x (H+L) = 73728
#define SMEM_GEMM (SM_A + 4*QBUF)           // 130048 B

__global__ void __launch_bounds__(256, 1)
k_gemm(const float* __restrict__ inp, const float* __restrict__ Wk,
       const float* __restrict__ We) {
    extern __shared__ char smem[];
    const unsigned sb = smem_u32(smem);
    unsigned* Mb = (unsigned*)smem;
    const int t = threadIdx.x, w = t >> 5, lane = t & 31;
    const int gid = lane >> 2, tig = lane & 3;

    // ---- one-time: build split-bf16 B fragments in smem ----
    for (int idx = t; idx < 2 * 16 * 6 * 32; idx += 256) {
        const int l2 = idx & 31;
        const int nt = (idx >> 5) % 6;
        const int ks = (idx >> 5) / 6 % 16;
        const int s  = idx / (32 * 6 * 16);
        const int n  = nt * 8 + (l2 >> 2);
        const int k0 = ks * 16 + (l2 & 3) * 2;
        const float* wrow = (n < 32) ? (Wk + (size_t)n * 256) : (We + (size_t)(n - 32) * 256);
        float v0 = wrow[k0], v1 = wrow[k0 + 1], v2 = wrow[k0 + 8], v3 = wrow[k0 + 9];
        unsigned p0, p1;
        if (s == 0) {
            CVT_BF2(p0, v0, v1); CVT_BF2(p1, v2, v3);
        } else {
            unsigned h0, h1;
            CVT_BF2(h0, v0, v1); CVT_BF2(h1, v2, v3);
            const float e0 = v0 - __uint_as_float(h0 << 16);
            const float e1 = v1 - __uint_as_float(h0 & 0xFFFF0000u);
            const float e2 = v2 - __uint_as_float(h1 << 16);
            const float e3 = v3 - __uint_as_float(h1 & 0xFFFF0000u);
            CVT_BF2(p0, e0, e1); CVT_BF2(p1, e2, e3);
        }
        const unsigned addr = sb + SM_BF + (unsigned)(((s * 6 + nt) * 32 + l2) * BLANE_B + ks * 8);
        asm volatile("st.shared.v2.b32 [%0], {%1,%2};" :: "r"(addr), "r"(p0), "r"(p1) : "memory");
    }
    Mb[t] = 0u;
    __syncthreads();

    const int cq = t & 15;          // float4 col within quarter
    const int rb = (t >> 4) * 8;    // row base (8 rows per thread)
    const unsigned lmrow = (unsigned)((w * 16 + (lane & 15)) * APITCH + ((lane >> 4) << 4));

    float4 v[8];
    // prologue: load tile(blockIdx) quarter 0
    {
        const float* base = inp + (size_t)blockIdx.x * 32768 + cq * 4;
#pragma unroll
        for (int i = 0; i < 8; i++) v[i] = *(const float4*)(base + (size_t)(rb + i) * 256);
    }

    int pb = 0;
    for (int tt = blockIdx.x; tt < NT; tt += gridDim.x) {
        const int r0 = tt * 128, b = tt >> 4;
        float d[6][4];
#pragma unroll
        for (int nt = 0; nt < 6; nt++)
#pragma unroll
            for (int q = 0; q < 4; q++) d[nt][q] = 0.f;

#pragma unroll
        for (int q = 0; q < 4; q++) {
            // ---- convert + store v -> buf[pb], per-column max ----
            {
                const unsigned bh = sb + SM_A + pb * (2 * QBUF);
                const unsigned bl = bh + QBUF;
                float mx0 = -3.4e38f, mx1 = mx0, mx2 = mx0, mx3 = mx0;
#pragma unroll
                for (int i = 0; i < 8; i++) {
                    const float4 vv = v[i];
                    mx0 = fmaxf(mx0, vv.x); mx1 = fmaxf(mx1, vv.y);
                    mx2 = fmaxf(mx2, vv.z); mx3 = fmaxf(mx3, vv.w);
                    unsigned h01, h23, l01, l23;
                    CVT_BF2(h01, vv.x, vv.y); CVT_BF2(h23, vv.z, vv.w);
                    const float e0 = vv.x - __uint_as_float(h01 << 16);
                    const float e1 = vv.y - __uint_as_float(h01 & 0xFFFF0000u);
                    const float e2 = vv.z - __uint_as_float(h23 << 16);
                    const float e3 = vv.w - __uint_as_float(h23 & 0xFFFF0000u);
                    CVT_BF2(l01, e0, e1); CVT_BF2(l23, e2, e3);
                    const unsigned off = (unsigned)((rb + i) * APITCH + cq * 8);
                    asm volatile("st.shared.v2.b32 [%0], {%1,%2};" :: "r"(bh + off), "r"(h01), "r"(h23) : "memory");
                    asm volatile("st.shared.v2.b32 [%0], {%1,%2};" :: "r"(bl + off), "r"(l01), "r"(l23) : "memory");
                }
                atomicMax(&Mb[q * 64 + cq * 4 + 0], encf(mx0));
                atomicMax(&Mb[q * 64 + cq * 4 + 1], encf(mx1));
                atomicMax(&Mb[q * 64 + cq * 4 + 2], encf(mx2));
                atomicMax(&Mb[q * 64 + cq * 4 + 3], encf(mx3));
            }
            __syncthreads();

            // ---- issue next quarter's loads (covered by MMA below) ----
            {
                const int nq = (q + 1) & 3;
                const int ntt = (q == 3) ? tt + (int)gridDim.x : tt;
                if (ntt < NT) {
                    const float* base = inp + (size_t)ntt * 32768 + nq * 64 + cq * 4;
#pragma unroll
                    for (int i = 0; i < 8; i++) v[i] = *(const float4*)(base + (size_t)(rb + i) * 256);
                }
            }

            // ---- MMA on buf[pb]: 4 local k-steps ----
            {
                const unsigned bh = sb + SM_A + pb * (2 * QBUF);
                const unsigned bl = bh + QBUF;
#pragma unroll
                for (int kp = 0; kp < 2; kp++) {
                    const int ksg = q * 4 + kp * 2;
                    unsigned ah0[4], al0[4], ah1[4], al1[4];
                    ldm_x4(ah0, bh + lmrow + kp * 64);
                    ldm_x4(al0, bl + lmrow + kp * 64);
                    ldm_x4(ah1, bh + lmrow + kp * 64 + 32);
                    ldm_x4(al1, bl + lmrow + kp * 64 + 32);
                    const unsigned bbf = sb + SM_BF + lane * BLANE_B + ksg * 8;
#pragma unroll
                    for (int nt = 0; nt < 6; nt++) {
                        unsigned bhf[4], blf[4];
                        asm volatile("ld.shared.v4.b32 {%0,%1,%2,%3}, [%4];"
                                     : "=r"(bhf[0]), "=r"(bhf[1]), "=r"(bhf[2]), "=r"(bhf[3])
                                     : "r"(bbf + nt * 32 * BLANE_B));
                        asm volatile("ld.shared.v4.b32 {%0,%1,%2,%3}, [%4];"
                                     : "=r"(blf[0]), "=r"(blf[1]), "=r"(blf[2]), "=r"(blf[3])
                                     : "r"(bbf + (6 + nt) * 32 * BLANE_B));
                        mma_bf16(d[nt], ah0, bhf);
                        mma_bf16(d[nt], ah0, blf);
                        mma_bf16(d[nt], al0, bhf);
                        mma_bf16(d[nt], ah1, bhf + 2);
                        mma_bf16(d[nt], ah1, blf + 2);
                        mma_bf16(d[nt], al1, bhf + 2);
                    }
                }
            }
            pb ^= 1;
        }

        // ---- epilogue: D fragments -> g_keys / g_evals ----
        {
            const int row0 = r0 + w * 16 + gid;
#pragma unroll
            for (int nt = 0; nt < 6; nt++) {
                const int c = nt * 8 + tig * 2;
                if (nt < 4) {
                    *(float2*)(g_keys + (size_t)row0 * 32 + c)       = make_float2(d[nt][0], d[nt][1]);
                    *(float2*)(g_keys + (size_t)(row0 + 8) * 32 + c) = make_float2(d[nt][2], d[nt][3]);
                } else {
                    *(float2*)(g_evals + (size_t)row0 * 16 + (c - 32))       = make_float2(d[nt][0], d[nt][1]);
                    *(float2*)(g_evals + (size_t)(row0 + 8) * 16 + (c - 32)) = make_float2(d[nt][2], d[nt][3]);
                }
            }
        }
        // ---- per-tile column max -> global pooled ----
        atomicMax(&g_pooled_enc[b * 256 + t], Mb[t]);
        __syncthreads();
        Mb[t] = 0u;
        __syncthreads();
    }
}

// ---------------------------------------------------------------------------
// K3: q = pooled @ [Wq0;Wq1]^T  — weight-stationary: 128 blocks x 8 cols
// ---------------------------------------------------------------------------
#define QW_STRIDE 268
__global__ void __launch_bounds__(256)
k_q(const float* __restrict__ Wq0, const float* __restrict__ Wq1) {
    __shared__ float Ws[8 * QW_STRIDE];
    const int t = threadIdx.x;
    const int c0 = blockIdx.x * 8;
    for (int idx = t; idx < 8 * 256; idx += 256) {
        const int row = idx >> 8, k = idx & 255;
        const int o = c0 + row;
        Ws[row * QW_STRIDE + k] = (o < 512) ? Wq0[(size_t)o * 256 + k]
                                            : Wq1[(size_t)(o - 512) * 256 + k];
    }
    __syncthreads();
    const int col = t & 7, gs = t >> 3;
    const float4* w4 = (const float4*)(Ws + col * QW_STRIDE);
#pragma unroll
    for (int kk = 0; kk < 4; kk++) {
        const int g = gs + 32 * kk;
        const uint4* p4 = (const uint4*)(g_pooled_enc + g * 256);
        float acc = 0.f;
#pragma unroll 8
        for (int j = 0; j < 64; j++) {
            const uint4 e = p4[j];
            const float4 w = w4[j];
            acc = fmaf(decf(e.x), w.x, acc);
            acc = fmaf(decf(e.y), w.y, acc);
            acc = fmaf(decf(e.z), w.z, acc);
            acc = fmaf(decf(e.w), w.w, acc);
        }
        g_q[g * 1024 + c0 + col] = acc;
    }
}

// ---------------------------------------------------------------------------
// K4a: split-softmax partials (round-5 config: 32 vh per block, 4 per warp)
// ---------------------------------------------------------------------------
#define KS_STRIDE 36
#define ES_STRIDE 20
#define SMEM_ATTN ((CHUNK*KS_STRIDE + CHUNK*ES_STRIDE + 32*32) * 4)

__global__ void __launch_bounds__(256, 2)
k_attn_part() {
    extern __shared__ float sm[];
    float* ks = sm;
    float* es = ks + CHUNK * KS_STRIDE;
    float* qs = es + CHUNK * ES_STRIDE;

    const int b = blockIdx.x, ch = blockIdx.y, t = threadIdx.x;
    const int n0 = ch * CHUNK;
    const float* keysb = g_keys  + ((size_t)b * Ng + n0) * 32;
    const float* eb    = g_evals + ((size_t)b * Ng + n0) * 16;

    for (int idx = t; idx < CHUNK * 8; idx += 256) {
        const int n = idx >> 3, k4 = idx & 7;
        ((float4*)(ks + n * KS_STRIDE))[k4] = ((const float4*)keysb)[idx];
    }
    for (int idx = t; idx < CHUNK * 4; idx += 256) {
        const int n = idx >> 2, r4 = idx & 3;
        ((float4*)(es + n * ES_STRIDE))[r4] = ((const float4*)eb)[idx];
    }
    for (int idx = t; idx < 1024; idx += 256)
        qs[idx] = g_q[b * 1024 + idx];
    __syncthreads();

    const int g  = t & 31;
    const int vq = t >> 5;

    float l[4][8];
#pragma unroll
    for (int vv = 0; vv < 4; vv++)
#pragma unroll
        for (int i = 0; i < 8; i++) l[vv][i] = 0.f;

#pragma unroll
    for (int k4 = 0; k4 < 8; k4++) {
        float4 q4[4];
#pragma unroll
        for (int vv = 0; vv < 4; vv++)
            q4[vv] = ((const float4*)(qs + (vq * 4 + vv) * 32))[k4];
#pragma unroll
        for (int i = 0; i < 8; i++) {
            const float4 kv = ((const float4*)(ks + (g + 32 * i) * KS_STRIDE))[k4];
#pragma unroll
            for (int vv = 0; vv < 4; vv++) {
                l[vv][i] = fmaf(q4[vv].x, kv.x, l[vv][i]);
                l[vv][i] = fmaf(q4[vv].y, kv.y, l[vv][i]);
                l[vv][i] = fmaf(q4[vv].z, kv.z, l[vv][i]);
                l[vv][i] = fmaf(q4[vv].w, kv.w, l[vv][i]);
            }
        }
    }

    float m[4], s[4];
#pragma unroll
    for (int vv = 0; vv < 4; vv++) {
        float mx = l[vv][0];
#pragma unroll
        for (int i = 1; i < 8; i++) mx = fmaxf(mx, l[vv][i]);
#pragma unroll
        for (int o = 16; o; o >>= 1) mx = fmaxf(mx, __shfl_xor_sync(0xffffffffu, mx, o));
        m[vv] = mx;
        float ss = 0.f;
#pragma unroll
        for (int i = 0; i < 8; i++) {
            const float e = __expf(l[vv][i] - mx);
            l[vv][i] = e;
            ss += e;
        }
#pragma unroll
        for (int o = 16; o; o >>= 1) ss += __shfl_xor_sync(0xffffffffu, ss, o);
        s[vv] = ss;
    }

    float acc[4][16];
#pragma unroll
    for (int vv = 0; vv < 4; vv++)
#pragma unroll
        for (int r = 0; r < 16; r++) acc[vv][r] = 0.f;

#pragma unroll
    for (int i = 0; i < 8; i++) {
        const float4* erow = (const float4*)(es + (g + 32 * i) * ES_STRIDE);
        float4 e0 = erow[0], e1 = erow[1], e2 = erow[2], e3 = erow[3];
#pragma unroll
        for (int vv = 0; vv < 4; vv++) {
            const float ev = l[vv][i];
            acc[vv][0]  = fmaf(ev, e0.x, acc[vv][0]);
            acc[vv][1]  = fmaf(ev, e0.y, acc[vv][1]);
            acc[vv][2]  = fmaf(ev, e0.z, acc[vv][2]);
            acc[vv][3]  = fmaf(ev, e0.w, acc[vv][3]);
            acc[vv][4]  = fmaf(ev, e1.x, acc[vv][4]);
            acc[vv][5]  = fmaf(ev, e1.y, acc[vv][5]);
            acc[vv][6]  = fmaf(ev, e1.z, acc[vv][6]);
            acc[vv][7]  = fmaf(ev, e1.w, acc[vv][7]);
            acc[vv][8]  = fmaf(ev, e2.x, acc[vv][8]);
            acc[vv][9]  = fmaf(ev, e2.y, acc[vv][9]);
            acc[vv][10] = fmaf(ev, e2.z, acc[vv][10]);
            acc[vv][11] = fmaf(ev, e2.w, acc[vv][11]);
            acc[vv][12] = fmaf(ev, e3.x, acc[vv][12]);
            acc[vv][13] = fmaf(ev, e3.y, acc[vv][13]);
            acc[vv][14] = fmaf(ev, e3.z, acc[vv][14]);
            acc[vv][15] = fmaf(ev, e3.w, acc[vv][15]);
        }
    }

#pragma unroll
    for (int vv = 0; vv < 4; vv++)
#pragma unroll
        for (int r = 0; r < 16; r++) {
            float a = acc[vv][r];
#pragma unroll
            for (int o = 16; o; o >>= 1) a += __shfl_xor_sync(0xffffffffu, a, o);
            acc[vv][r] = a;
        }

    if (g == 0) {
        float* p = g_part + (((size_t)(b * NCHUNK + ch) * 32) + vq * 4) * 18;
#pragma unroll
        for (int vv = 0; vv < 4; vv++) {
            p[vv * 18 + 0] = m[vv];
            p[vv * 18 + 1] = s[vv];
#pragma unroll
            for (int r = 0; r < 16; r++) p[vv * 18 + 2 + r] = acc[vv][r];
        }
    }
}

__global__ void k_attn_red() {
    const int b = blockIdx.x, vh = threadIdx.x;
    const float* base = g_part + (size_t)b * NCHUNK * 32 * 18 + vh * 18;
    float M = __int_as_float(0xff800000);
#pragma unroll
    for (int c = 0; c < NCHUNK; c++) M = fmaxf(M, base[c * 32 * 18]);
    float S = 0.f, acc[16];
#pragma unroll
    for (int r = 0; r < 16; r++) acc[r] = 0.f;
#pragma unroll
    for (int c = 0; c < NCHUNK; c++) {
        const float* p = base + c * 32 * 18;
        const float w = __expf(p[0] - M);
        S = fmaf(p[1], w, S);
#pragma unroll
        for (int r = 0; r < 16; r++) acc[r] = fmaf(p[2 + r], w, acc[r]);
    }
    const float inv = 1.f / S;
#pragma unroll
    for (int r = 0; r < 16; r++)
        g_embed[b * 512 + vh * 16 + r] = acc[r] * inv;
}

// ---------------------------------------------------------------------------
// K5: out = leaky((embed0-embed1) @ Wout^T + bout) — 32 blocks x 8 dims
// ---------------------------------------------------------------------------
__global__ void __launch_bounds__(256)
k_out(const float* __restrict__ Wout, const float* __restrict__ bout,
      float* __restrict__ out) {
    __shared__ float Ws[8 * QW_STRIDE];
    const int t = threadIdx.x;
    const int d0 = blockIdx.x * 8;
    for (int idx = t; idx < 8 * 256; idx += 256) {
        const int row = idx >> 8, k = idx & 255;
        Ws[row * QW_STRIDE + k] = Wout[(size_t)(d0 + row) * 256 + k];
    }
    __syncthreads();
    const int col = t & 7, gs = t >> 3;
    const int d = d0 + col;
    const float bv = bout[d];
    const float4* w4 = (const float4*)(Ws + col * QW_STRIDE);
#pragma unroll
    for (int kk = 0; kk < 4; kk++) {
        const int g = gs + 32 * kk;
        const float4* e0p = (const float4*)(g_embed + g * 512);
        const float4* e1p = (const float4*)(g_embed + g * 512 + 256);
        float acc = bv;
#pragma unroll 8
        for (int j = 0; j < 64; j++) {
            const float4 a = e0p[j], bq = e1p[j], w = w4[j];
            acc = fmaf(a.x - bq.x, w.x, acc);
            acc = fmaf(a.y - bq.y, w.y, acc);
            acc = fmaf(a.z - bq.z, w.z, acc);
            acc = fmaf(a.w - bq.w, w.w, acc);
        }
        out[g * 256 + d] = acc >= 0.f ? acc : 0.01f * acc;
    }
}

extern "C" void kernel_launch(void* const* d_in, const int* in_sizes, int n_in,
                              void* d_out, int out_size) {
    const float* inp  = (const float*)d_in[0];
    const float* Wk   = (const float*)d_in[2];
    const float* Wq0  = (const float*)d_in[3];
    const float* Wq1  = (const float*)d_in[4];
    const float* We   = (const float*)d_in[5];
    const float* Wout = (const float*)d_in[6];
    const float* bout = (const float*)d_in[7];
    float* out = (float*)d_out;

    cudaFuncSetAttribute(k_gemm, cudaFuncAttributeMaxDynamicSharedMemorySize, SMEM_GEMM);
    cudaFuncSetAttribute(k_attn_part, cudaFuncAttributeMaxDynamicSharedMemorySize, SMEM_ATTN);

    k_init<<<128, 256>>>();
    k_gemm<<<148, 256, SMEM_GEMM>>>(inp, Wk, We);
    k_q<<<128, 256>>>(Wq0, Wq1);
    k_attn_part<<<dim3(Bg, NCHUNK), 256, SMEM_ATTN>>>();
    k_attn_red<<<Bg, 32>>>();
    k_out<<<32, 256>>>(Wout, bout, out);
}

// round 8
// speedup vs baseline: 2.5868x; 1.0267x over previous
#include <cuda_runtime.h>

#define Bg 128
#define Ng 2048
#define Dd 256
#define Hh 16
#define Kk 32
#define Rr 16
#define BN (Bg*Ng)
#define NT (BN/128)
#define NCHUNK 8
#define CHUNK 256

// scratch (static device arrays; no allocation)
__device__ unsigned g_pooled_enc[Bg*Dd];
__device__ float    g_keys [BN*Kk];     // [B,N,K]
__device__ float    g_evals[BN*Rr];     // [B,N,R]
__device__ float    g_q    [Bg*2*Hh*Kk];
__device__ float    g_embed[Bg*2*Hh*Rr];
__device__ float    g_part [Bg*NCHUNK*32*18];

__device__ __forceinline__ unsigned encf(float f) {
    unsigned u = __float_as_uint(f);
    return (u & 0x80000000u) ? ~u : (u | 0x80000000u);
}
__device__ __forceinline__ float decf(unsigned u) {
    u = (u & 0x80000000u) ? (u & 0x7FFFFFFFu) : ~u;
    return __uint_as_float(u);
}

__global__ void k_init() {
    g_pooled_enc[blockIdx.x * 256 + threadIdx.x] = 0u;
}

// ======================= baseline-ISA tensor helpers =======================
__device__ __forceinline__ unsigned smem_u32(const void* p) {
    unsigned a;
    asm("{ .reg .u64 t; cvta.to.shared.u64 t, %1; cvt.u32.u64 %0, t; }" : "=r"(a) : "l"(p));
    return a;
}
#define CVT_BF2(r, lo, hi) asm("cvt.rn.satfinite.bf16x2.f32 %0, %1, %2;" : "=r"(r) : "f"(hi), "f"(lo))

__device__ __forceinline__ void ldm_x4(unsigned* a, unsigned addr) {
    asm volatile("ldmatrix.sync.aligned.m8n8.x4.shared.b16 {%0,%1,%2,%3}, [%4];"
                 : "=r"(a[0]), "=r"(a[1]), "=r"(a[2]), "=r"(a[3]) : "r"(addr));
}
__device__ __forceinline__ void mma_bf16(float* d, const unsigned* a, const unsigned* b) {
    asm volatile(
        "mma.sync.aligned.m16n8k16.row.col.f32.bf16.bf16.f32 "
        "{%0,%1,%2,%3}, {%4,%5,%6,%7}, {%8,%9}, {%0,%1,%2,%3};"
        : "+f"(d[0]), "+f"(d[1]), "+f"(d[2]), "+f"(d[3])
        : "r"(a[0]), "r"(a[1]), "r"(a[2]), "r"(a[3]), "r"(b[0]), "r"(b[1]));
}

// ---------------------------------------------------------------------------
// K2: pipelined persistent bf16-split3 GEMM: keys|e = x @ [Wk;We]^T (+max)
// Pooling via register maxima + padded smem transpose + one global RED/tile
// (NO smem atomics in the hot loop).
// ---------------------------------------------------------------------------
#define BLANE_B  144
#define APITCH   144                        // 64 bf16 = 128 B + 16 pad
#define QBUF     (128*APITCH)               // 18432 B per split
#define MS_PITCH 17
#define SM_MS    0                          // float[256][17] = 17408 B
#define SM_BF    17408                      // B frags 55296 B
#define SM_A     (SM_BF + 55296)            // 2 bufs x (H+L) = 73728
#define SMEM_GEMM (SM_A + 4*QBUF)           // 146432 B

__global__ void __launch_bounds__(256, 1)
k_gemm(const float* __restrict__ inp, const float* __restrict__ Wk,
       const float* __restrict__ We) {
    extern __shared__ char smem[];
    const unsigned sb = smem_u32(smem);
    float* Ms = (float*)smem;
    const int t = threadIdx.x, w = t >> 5, lane = t & 31;
    const int gid = lane >> 2, tig = lane & 3;

    // ---- one-time: build split-bf16 B fragments in smem ----
    for (int idx = t; idx < 2 * 16 * 6 * 32; idx += 256) {
        const int l2 = idx & 31;
        const int nt = (idx >> 5) % 6;
        const int ks = (idx >> 5) / 6 % 16;
        const int s  = idx / (32 * 6 * 16);
        const int n  = nt * 8 + (l2 >> 2);
        const int k0 = ks * 16 + (l2 & 3) * 2;
        const float* wrow = (n < 32) ? (Wk + (size_t)n * 256) : (We + (size_t)(n - 32) * 256);
        float v0 = wrow[k0], v1 = wrow[k0 + 1], v2 = wrow[k0 + 8], v3 = wrow[k0 + 9];
        unsigned p0, p1;
        if (s == 0) {
            CVT_BF2(p0, v0, v1); CVT_BF2(p1, v2, v3);
        } else {
            unsigned h0, h1;
            CVT_BF2(h0, v0, v1); CVT_BF2(h1, v2, v3);
            const float e0 = v0 - __uint_as_float(h0 << 16);
            const float e1 = v1 - __uint_as_float(h0 & 0xFFFF0000u);
            const float e2 = v2 - __uint_as_float(h1 << 16);
            const float e3 = v3 - __uint_as_float(h1 & 0xFFFF0000u);
            CVT_BF2(p0, e0, e1); CVT_BF2(p1, e2, e3);
        }
        const unsigned addr = sb + SM_BF + (unsigned)(((s * 6 + nt) * 32 + l2) * BLANE_B + ks * 8);
        asm volatile("st.shared.v2.b32 [%0], {%1,%2};" :: "r"(addr), "r"(p0), "r"(p1) : "memory");
    }
    __syncthreads();

    const int cq = t & 15;          // float4 col within quarter
    const int rb = (t >> 4) * 8;    // row base (8 rows per thread)
    const int jm = t >> 4;          // max-transpose column 0..15
    const unsigned lmrow = (unsigned)((w * 16 + (lane & 15)) * APITCH + ((lane >> 4) << 4));

    float4 v[8];
    // prologue: load tile(blockIdx) quarter 0
    {
        const float* base = inp + (size_t)blockIdx.x * 32768 + cq * 4;
#pragma unroll
        for (int i = 0; i < 8; i++) v[i] = *(const float4*)(base + (size_t)(rb + i) * 256);
    }

    int pb = 0;
    for (int tt = blockIdx.x; tt < NT; tt += gridDim.x) {
        const int r0 = tt * 128, b = tt >> 4;
        float d[6][4];
#pragma unroll
        for (int nt = 0; nt < 6; nt++)
#pragma unroll
            for (int q = 0; q < 4; q++) d[nt][q] = 0.f;

#pragma unroll
        for (int q = 0; q < 4; q++) {
            // ---- convert + store v -> buf[pb], register column max ----
            {
                const unsigned bh = sb + SM_A + pb * (2 * QBUF);
                const unsigned bl = bh + QBUF;
                float mx0 = -3.4e38f, mx1 = mx0, mx2 = mx0, mx3 = mx0;
#pragma unroll
                for (int i = 0; i < 8; i++) {
                    const float4 vv = v[i];
                    mx0 = fmaxf(mx0, vv.x); mx1 = fmaxf(mx1, vv.y);
                    mx2 = fmaxf(mx2, vv.z); mx3 = fmaxf(mx3, vv.w);
                    unsigned h01, h23, l01, l23;
                    CVT_BF2(h01, vv.x, vv.y); CVT_BF2(h23, vv.z, vv.w);
                    const float e0 = vv.x - __uint_as_float(h01 << 16);
                    const float e1 = vv.y - __uint_as_float(h01 & 0xFFFF0000u);
                    const float e2 = vv.z - __uint_as_float(h23 << 16);
                    const float e3 = vv.w - __uint_as_float(h23 & 0xFFFF0000u);
                    CVT_BF2(l01, e0, e1); CVT_BF2(l23, e2, e3);
                    const unsigned off = (unsigned)((rb + i) * APITCH + cq * 8);
                    asm volatile("st.shared.v2.b32 [%0], {%1,%2};" :: "r"(bh + off), "r"(h01), "r"(h23) : "memory");
                    asm volatile("st.shared.v2.b32 [%0], {%1,%2};" :: "r"(bl + off), "r"(l01), "r"(l23) : "memory");
                }
                // plain stores into padded transpose buffer (no atomics)
                const int col0 = q * 64 + cq * 4;
                Ms[(col0 + 0) * MS_PITCH + jm] = mx0;
                Ms[(col0 + 1) * MS_PITCH + jm] = mx1;
                Ms[(col0 + 2) * MS_PITCH + jm] = mx2;
                Ms[(col0 + 3) * MS_PITCH + jm] = mx3;
            }
            __syncthreads();

            // ---- issue next quarter's loads (covered by MMA below) ----
            {
                const int nq = (q + 1) & 3;
                const int ntt = (q == 3) ? tt + (int)gridDim.x : tt;
                if (ntt < NT) {
                    const float* base = inp + (size_t)ntt * 32768 + nq * 64 + cq * 4;
#pragma unroll
                    for (int i = 0; i < 8; i++) v[i] = *(const float4*)(base + (size_t)(rb + i) * 256);
                }
            }

            // ---- MMA on buf[pb]: 4 local k-steps ----
            {
                const unsigned bh = sb + SM_A + pb * (2 * QBUF);
                const unsigned bl = bh + QBUF;
#pragma unroll
                for (int kp = 0; kp < 2; kp++) {
                    const int ksg = q * 4 + kp * 2;
                    unsigned ah0[4], al0[4], ah1[4], al1[4];
                    ldm_x4(ah0, bh + lmrow + kp * 64);
                    ldm_x4(al0, bl + lmrow + kp * 64);
                    ldm_x4(ah1, bh + lmrow + kp * 64 + 32);
                    ldm_x4(al1, bl + lmrow + kp * 64 + 32);
                    const unsigned bbf = sb + SM_BF + lane * BLANE_B + ksg * 8;
#pragma unroll
                    for (int nt = 0; nt < 6; nt++) {
                        unsigned bhf[4], blf[4];
                        asm volatile("ld.shared.v4.b32 {%0,%1,%2,%3}, [%4];"
                                     : "=r"(bhf[0]), "=r"(bhf[1]), "=r"(bhf[2]), "=r"(bhf[3])
                                     : "r"(bbf + nt * 32 * BLANE_B));
                        asm volatile("ld.shared.v4.b32 {%0,%1,%2,%3}, [%4];"
                                     : "=r"(blf[0]), "=r"(blf[1]), "=r"(blf[2]), "=r"(blf[3])
                                     : "r"(bbf + (6 + nt) * 32 * BLANE_B));
                        mma_bf16(d[nt], ah0, bhf);
                        mma_bf16(d[nt], ah0, blf);
                        mma_bf16(d[nt], al0, bhf);
                        mma_bf16(d[nt], ah1, bhf + 2);
                        mma_bf16(d[nt], ah1, blf + 2);
                        mma_bf16(d[nt], al1, bhf + 2);
                    }
                }
            }
            pb ^= 1;
        }

        // ---- epilogue: D fragments -> g_keys / g_evals ----
        {
            const int row0 = r0 + w * 16 + gid;
#pragma unroll
            for (int nt = 0; nt < 6; nt++) {
                const int c = nt * 8 + tig * 2;
                if (nt < 4) {
                    *(float2*)(g_keys + (size_t)row0 * 32 + c)       = make_float2(d[nt][0], d[nt][1]);
                    *(float2*)(g_keys + (size_t)(row0 + 8) * 32 + c) = make_float2(d[nt][2], d[nt][3]);
                } else {
                    *(float2*)(g_evals + (size_t)row0 * 16 + (c - 32))       = make_float2(d[nt][0], d[nt][1]);
                    *(float2*)(g_evals + (size_t)(row0 + 8) * 16 + (c - 32)) = make_float2(d[nt][2], d[nt][3]);
                }
            }
        }
        // ---- tile column max: reduce transpose buffer, one global RED ----
        {
            float m = Ms[t * MS_PITCH];
#pragma unroll
            for (int j = 1; j < 16; j++) m = fmaxf(m, Ms[t * MS_PITCH + j]);
            atomicMax(&g_pooled_enc[b * 256 + t], encf(m));
        }
        __syncthreads();
    }
}

// ---------------------------------------------------------------------------
// K3: q = pooled @ [Wq0;Wq1]^T  — weight-stationary: 128 blocks x 8 cols
// ---------------------------------------------------------------------------
#define QW_STRIDE 268
__global__ void __launch_bounds__(256)
k_q(const float* __restrict__ Wq0, const float* __restrict__ Wq1) {
    __shared__ float Ws[8 * QW_STRIDE];
    const int t = threadIdx.x;
    const int c0 = blockIdx.x * 8;
    for (int idx = t; idx < 8 * 256; idx += 256) {
        const int row = idx >> 8, k = idx & 255;
        const int o = c0 + row;
        Ws[row * QW_STRIDE + k] = (o < 512) ? Wq0[(size_t)o * 256 + k]
                                            : Wq1[(size_t)(o - 512) * 256 + k];
    }
    __syncthreads();
    const int col = t & 7, gs = t >> 3;
    const float4* w4 = (const float4*)(Ws + col * QW_STRIDE);
#pragma unroll
    for (int kk = 0; kk < 4; kk++) {
        const int g = gs + 32 * kk;
        const uint4* p4 = (const uint4*)(g_pooled_enc + g * 256);
        float acc = 0.f;
#pragma unroll 8
        for (int j = 0; j < 64; j++) {
            const uint4 e = p4[j];
            const float4 w = w4[j];
            acc = fmaf(decf(e.x), w.x, acc);
            acc = fmaf(decf(e.y), w.y, acc);
            acc = fmaf(decf(e.z), w.z, acc);
            acc = fmaf(decf(e.w), w.w, acc);
        }
        g_q[g * 1024 + c0 + col] = acc;
    }
}

// ---------------------------------------------------------------------------
// K4a: split-softmax partials (round-5 config: 32 vh per block, 4 per warp)
// ---------------------------------------------------------------------------
#define KS_STRIDE 36
#define ES_STRIDE 20
#define SMEM_ATTN ((CHUNK*KS_STRIDE + CHUNK*ES_STRIDE + 32*32) * 4)

__global__ void __launch_bounds__(256, 2)
k_attn_part() {
    extern __shared__ float sm[];
    float* ks = sm;
    float* es = ks + CHUNK * KS_STRIDE;
    float* qs = es + CHUNK * ES_STRIDE;

    const int b = blockIdx.x, ch = blockIdx.y, t = threadIdx.x;
    const int n0 = ch * CHUNK;
    const float* keysb = g_keys  + ((size_t)b * Ng + n0) * 32;
    const float* eb    = g_evals + ((size_t)b * Ng + n0) * 16;

    for (int idx = t; idx < CHUNK * 8; idx += 256) {
        const int n = idx >> 3, k4 = idx & 7;
        ((float4*)(ks + n * KS_STRIDE))[k4] = ((const float4*)keysb)[idx];
    }
    for (int idx = t; idx < CHUNK * 4; idx += 256) {
        const int n = idx >> 2, r4 = idx & 3;
        ((float4*)(es + n * ES_STRIDE))[r4] = ((const float4*)eb)[idx];
    }
    for (int idx = t; idx < 1024; idx += 256)
        qs[idx] = g_q[b * 1024 + idx];
    __syncthreads();

    const int g  = t & 31;
    const int vq = t >> 5;

    float l[4][8];
#pragma unroll
    for (int vv = 0; vv < 4; vv++)
#pragma unroll
        for (int i = 0; i < 8; i++) l[vv][i] = 0.f;

#pragma unroll
    for (int k4 = 0; k4 < 8; k4++) {
        float4 q4[4];
#pragma unroll
        for (int vv = 0; vv < 4; vv++)
            q4[vv] = ((const float4*)(qs + (vq * 4 + vv) * 32))[k4];
#pragma unroll
        for (int i = 0; i < 8; i++) {
            const float4 kv = ((const float4*)(ks + (g + 32 * i) * KS_STRIDE))[k4];
#pragma unroll
            for (int vv = 0; vv < 4; vv++) {
                l[vv][i] = fmaf(q4[vv].x, kv.x, l[vv][i]);
                l[vv][i] = fmaf(q4[vv].y, kv.y, l[vv][i]);
                l[vv][i] = fmaf(q4[vv].z, kv.z, l[vv][i]);
                l[vv][i] = fmaf(q4[vv].w, kv.w, l[vv][i]);
            }
        }
    }

    float m[4], s[4];
#pragma unroll
    for (int vv = 0; vv < 4; vv++) {
        float mx = l[vv][0];
#pragma unroll
        for (int i = 1; i < 8; i++) mx = fmaxf(mx, l[vv][i]);
#pragma unroll
        for (int o = 16; o; o >>= 1) mx = fmaxf(mx, __shfl_xor_sync(0xffffffffu, mx, o));
        m[vv] = mx;
        float ss = 0.f;
#pragma unroll
        for (int i = 0; i < 8; i++) {
            const float e = __expf(l[vv][i] - mx);
            l[vv][i] = e;
            ss += e;
        }
#pragma unroll
        for (int o = 16; o; o >>= 1) ss += __shfl_xor_sync(0xffffffffu, ss, o);
        s[vv] = ss;
    }

    float acc[4][16];
#pragma unroll
    for (int vv = 0; vv < 4; vv++)
#pragma unroll
        for (int r = 0; r < 16; r++) acc[vv][r] = 0.f;

#pragma unroll
    for (int i = 0; i < 8; i++) {
        const float4* erow = (const float4*)(es + (g + 32 * i) * ES_STRIDE);
        float4 e0 = erow[0], e1 = erow[1], e2 = erow[2], e3 = erow[3];
#pragma unroll
        for (int vv = 0; vv < 4; vv++) {
            const float ev = l[vv][i];
            acc[vv][0]  = fmaf(ev, e0.x, acc[vv][0]);
            acc[vv][1]  = fmaf(ev, e0.y, acc[vv][1]);
            acc[vv][2]  = fmaf(ev, e0.z, acc[vv][2]);
            acc[vv][3]  = fmaf(ev, e0.w, acc[vv][3]);
            acc[vv][4]  = fmaf(ev, e1.x, acc[vv][4]);
            acc[vv][5]  = fmaf(ev, e1.y, acc[vv][5]);
            acc[vv][6]  = fmaf(ev, e1.z, acc[vv][6]);
            acc[vv][7]  = fmaf(ev, e1.w, acc[vv][7]);
            acc[vv][8]  = fmaf(ev, e2.x, acc[vv][8]);
            acc[vv][9]  = fmaf(ev, e2.y, acc[vv][9]);
            acc[vv][10] = fmaf(ev, e2.z, acc[vv][10]);
            acc[vv][11] = fmaf(ev, e2.w, acc[vv][11]);
            acc[vv][12] = fmaf(ev, e3.x, acc[vv][12]);
            acc[vv][13] = fmaf(ev, e3.y, acc[vv][13]);
            acc[vv][14] = fmaf(ev, e3.z, acc[vv][14]);
            acc[vv][15] = fmaf(ev, e3.w, acc[vv][15]);
        }
    }

#pragma unroll
    for (int vv = 0; vv < 4; vv++)
#pragma unroll
        for (int r = 0; r < 16; r++) {
            float a = acc[vv][r];
#pragma unroll
            for (int o = 16; o; o >>= 1) a += __shfl_xor_sync(0xffffffffu, a, o);
            acc[vv][r] = a;
        }

    if (g == 0) {
        float* p = g_part + (((size_t)(b * NCHUNK + ch) * 32) + vq * 4) * 18;
#pragma unroll
        for (int vv = 0; vv < 4; vv++) {
            p[vv * 18 + 0] = m[vv];
            p[vv * 18 + 1] = s[vv];
#pragma unroll
            for (int r = 0; r < 16; r++) p[vv * 18 + 2 + r] = acc[vv][r];
        }
    }
}

__global__ void k_attn_red() {
    const int b = blockIdx.x, vh = threadIdx.x;
    const float* base = g_part + (size_t)b * NCHUNK * 32 * 18 + vh * 18;
    float M = __int_as_float(0xff800000);
#pragma unroll
    for (int c = 0; c < NCHUNK; c++) M = fmaxf(M, base[c * 32 * 18]);
    float S = 0.f, acc[16];
#pragma unroll
    for (int r = 0; r < 16; r++) acc[r] = 0.f;
#pragma unroll
    for (int c = 0; c < NCHUNK; c++) {
        const float* p = base + c * 32 * 18;
        const float w = __expf(p[0] - M);
        S = fmaf(p[1], w, S);
#pragma unroll
        for (int r = 0; r < 16; r++) acc[r] = fmaf(p[2 + r], w, acc[r]);
    }
    const float inv = 1.f / S;
#pragma unroll
    for (int r = 0; r < 16; r++)
        g_embed[b * 512 + vh * 16 + r] = acc[r] * inv;
}

// ---------------------------------------------------------------------------
// K5: out = leaky((embed0-embed1) @ Wout^T + bout) — 32 blocks x 8 dims
// ---------------------------------------------------------------------------
__global__ void __launch_bounds__(256)
k_out(const float* __restrict__ Wout, const float* __restrict__ bout,
      float* __restrict__ out) {
    __shared__ float Ws[8 * QW_STRIDE];
    const int t = threadIdx.x;
    const int d0 = blockIdx.x * 8;
    for (int idx = t; idx < 8 * 256; idx += 256) {
        const int row = idx >> 8, k = idx & 255;
        Ws[row * QW_STRIDE + k] = Wout[(size_t)(d0 + row) * 256 + k];
    }
    __syncthreads();
    const int col = t & 7, gs = t >> 3;
    const int d = d0 + col;
    const float bv = bout[d];
    const float4* w4 = (const float4*)(Ws + col * QW_STRIDE);
#pragma unroll
    for (int kk = 0; kk < 4; kk++) {
        const int g = gs + 32 * kk;
        const float4* e0p = (const float4*)(g_embed + g * 512);
        const float4* e1p = (const float4*)(g_embed + g * 512 + 256);
        float acc = bv;
#pragma unroll 8
        for (int j = 0; j < 64; j++) {
            const float4 a = e0p[j], bq = e1p[j], w = w4[j];
            acc = fmaf(a.x - bq.x, w.x, acc);
            acc = fmaf(a.y - bq.y, w.y, acc);
            acc = fmaf(a.z - bq.z, w.z, acc);
            acc = fmaf(a.w - bq.w, w.w, acc);
        }
        out[g * 256 + d] = acc >= 0.f ? acc : 0.01f * acc;
    }
}

extern "C" void kernel_launch(void* const* d_in, const int* in_sizes, int n_in,
                              void* d_out, int out_size) {
    const float* inp  = (const float*)d_in[0];
    const float* Wk   = (const float*)d_in[2];
    const float* Wq0  = (const float*)d_in[3];
    const float* Wq1  = (const float*)d_in[4];
    const float* We   = (const float*)d_in[5];
    const float* Wout = (const float*)d_in[6];
    const float* bout = (const float*)d_in[7];
    float* out = (float*)d_out;

    cudaFuncSetAttribute(k_gemm, cudaFuncAttributeMaxDynamicSharedMemorySize, SMEM_GEMM);
    cudaFuncSetAttribute(k_attn_part, cudaFuncAttributeMaxDynamicSharedMemorySize, SMEM_ATTN);

    k_init<<<128, 256>>>();
    k_gemm<<<148, 256, SMEM_GEMM>>>(inp, Wk, We);
    k_q<<<128, 256>>>(Wq0, Wq1);
    k_attn_part<<<dim3(Bg, NCHUNK), 256, SMEM_ATTN>>>();
    k_attn_red<<<Bg, 32>>>();
    k_out<<<32, 256>>>(Wout, bout, out);
}

// round 9
// speedup vs baseline: 2.7572x; 1.0659x over previous
#include <cuda_runtime.h>

#define Bg 128
#define Ng 2048
#define Dd 256
#define Hh 16
#define Kk 32
#define Rr 16
#define BN (Bg*Ng)
#define NT (BN/128)
#define NCHUNK 8
#define CHUNK 256

// scratch (static device arrays; no allocation)
__device__ unsigned g_pooled_enc[Bg*Dd];
__device__ float    g_keys [BN*Kk];     // [B,N,K]
__device__ float    g_evals[BN*Rr];     // [B,N,R]
__device__ float    g_q    [Bg*2*Hh*Kk];
__device__ float    g_embed[Bg*2*Hh*Rr];
__device__ float    g_part [Bg*NCHUNK*32*18];

__device__ __forceinline__ unsigned encf(float f) {
    unsigned u = __float_as_uint(f);
    return (u & 0x80000000u) ? ~u : (u | 0x80000000u);
}
__device__ __forceinline__ float decf(unsigned u) {
    u = (u & 0x80000000u) ? (u & 0x7FFFFFFFu) : ~u;
    return __uint_as_float(u);
}

__global__ void k_init() {
    g_pooled_enc[blockIdx.x * 256 + threadIdx.x] = 0u;
}
// no-op launches to shift k_gemm into the ncu -s 5 -c 1 capture slot
__global__ void k_dummy() {}

// ======================= baseline-ISA tensor helpers =======================
__device__ __forceinline__ unsigned smem_u32(const void* p) {
    unsigned a;
    asm("{ .reg .u64 t; cvta.to.shared.u64 t, %1; cvt.u32.u64 %0, t; }" : "=r"(a) : "l"(p));
    return a;
}
#define CVT_BF2(r, lo, hi) asm("cvt.rn.satfinite.bf16x2.f32 %0, %1, %2;" : "=r"(r) : "f"(hi), "f"(lo))

__device__ __forceinline__ void ldm_x4(unsigned* a, unsigned addr) {
    asm volatile("ldmatrix.sync.aligned.m8n8.x4.shared.b16 {%0,%1,%2,%3}, [%4];"
                 : "=r"(a[0]), "=r"(a[1]), "=r"(a[2]), "=r"(a[3]) : "r"(addr));
}
__device__ __forceinline__ void mma_bf16(float* d, const unsigned* a, const unsigned* b) {
    asm volatile(
        "mma.sync.aligned.m16n8k16.row.col.f32.bf16.bf16.f32 "
        "{%0,%1,%2,%3}, {%4,%5,%6,%7}, {%8,%9}, {%0,%1,%2,%3};"
        : "+f"(d[0]), "+f"(d[1]), "+f"(d[2]), "+f"(d[3])
        : "r"(a[0]), "r"(a[1]), "r"(a[2]), "r"(a[3]), "r"(b[0]), "r"(b[1]));
}

// ---------------------------------------------------------------------------
// K2: pipelined persistent bf16-split3 GEMM (unchanged from round 8)
// ---------------------------------------------------------------------------
#define BLANE_B  144
#define APITCH   144
#define QBUF     (128*APITCH)
#define MS_PITCH 17
#define SM_MS    0
#define SM_BF    17408
#define SM_A     (SM_BF + 55296)
#define SMEM_GEMM (SM_A + 4*QBUF)

__global__ void __launch_bounds__(256, 1)
k_gemm(const float* __restrict__ inp, const float* __restrict__ Wk,
       const float* __restrict__ We) {
    extern __shared__ char smem[];
    const unsigned sb = smem_u32(smem);
    float* Ms = (float*)smem;
    const int t = threadIdx.x, w = t >> 5, lane = t & 31;
    const int gid = lane >> 2, tig = lane & 3;

    for (int idx = t; idx < 2 * 16 * 6 * 32; idx += 256) {
        const int l2 = idx & 31;
        const int nt = (idx >> 5) % 6;
        const int ks = (idx >> 5) / 6 % 16;
        const int s  = idx / (32 * 6 * 16);
        const int n  = nt * 8 + (l2 >> 2);
        const int k0 = ks * 16 + (l2 & 3) * 2;
        const float* wrow = (n < 32) ? (Wk + (size_t)n * 256) : (We + (size_t)(n - 32) * 256);
        float v0 = wrow[k0], v1 = wrow[k0 + 1], v2 = wrow[k0 + 8], v3 = wrow[k0 + 9];
        unsigned p0, p1;
        if (s == 0) {
            CVT_BF2(p0, v0, v1); CVT_BF2(p1, v2, v3);
        } else {
            unsigned h0, h1;
            CVT_BF2(h0, v0, v1); CVT_BF2(h1, v2, v3);
            const float e0 = v0 - __uint_as_float(h0 << 16);
            const float e1 = v1 - __uint_as_float(h0 & 0xFFFF0000u);
            const float e2 = v2 - __uint_as_float(h1 << 16);
            const float e3 = v3 - __uint_as_float(h1 & 0xFFFF0000u);
            CVT_BF2(p0, e0, e1); CVT_BF2(p1, e2, e3);
        }
        const unsigned addr = sb + SM_BF + (unsigned)(((s * 6 + nt) * 32 + l2) * BLANE_B + ks * 8);
        asm volatile("st.shared.v2.b32 [%0], {%1,%2};" :: "r"(addr), "r"(p0), "r"(p1) : "memory");
    }
    __syncthreads();

    const int cq = t & 15;
    const int rb = (t >> 4) * 8;
    const int jm = t >> 4;
    const unsigned lmrow = (unsigned)((w * 16 + (lane & 15)) * APITCH + ((lane >> 4) << 4));

    float4 v[8];
    {
        const float* base = inp + (size_t)blockIdx.x * 32768 + cq * 4;
#pragma unroll
        for (int i = 0; i < 8; i++) v[i] = *(const float4*)(base + (size_t)(rb + i) * 256);
    }

    int pb = 0;
    for (int tt = blockIdx.x; tt < NT; tt += gridDim.x) {
        const int r0 = tt * 128, b = tt >> 4;
        float d[6][4];
#pragma unroll
        for (int nt = 0; nt < 6; nt++)
#pragma unroll
            for (int q = 0; q < 4; q++) d[nt][q] = 0.f;

#pragma unroll
        for (int q = 0; q < 4; q++) {
            {
                const unsigned bh = sb + SM_A + pb * (2 * QBUF);
                const unsigned bl = bh + QBUF;
                float mx0 = -3.4e38f, mx1 = mx0, mx2 = mx0, mx3 = mx0;
#pragma unroll
                for (int i = 0; i < 8; i++) {
                    const float4 vv = v[i];
                    mx0 = fmaxf(mx0, vv.x); mx1 = fmaxf(mx1, vv.y);
                    mx2 = fmaxf(mx2, vv.z); mx3 = fmaxf(mx3, vv.w);
                    unsigned h01, h23, l01, l23;
                    CVT_BF2(h01, vv.x, vv.y); CVT_BF2(h23, vv.z, vv.w);
                    const float e0 = vv.x - __uint_as_float(h01 << 16);
                    const float e1 = vv.y - __uint_as_float(h01 & 0xFFFF0000u);
                    const float e2 = vv.z - __uint_as_float(h23 << 16);
                    const float e3 = vv.w - __uint_as_float(h23 & 0xFFFF0000u);
                    CVT_BF2(l01, e0, e1); CVT_BF2(l23, e2, e3);
                    const unsigned off = (unsigned)((rb + i) * APITCH + cq * 8);
                    asm volatile("st.shared.v2.b32 [%0], {%1,%2};" :: "r"(bh + off), "r"(h01), "r"(h23) : "memory");
                    asm volatile("st.shared.v2.b32 [%0], {%1,%2};" :: "r"(bl + off), "r"(l01), "r"(l23) : "memory");
                }
                const int col0 = q * 64 + cq * 4;
                Ms[(col0 + 0) * MS_PITCH + jm] = mx0;
                Ms[(col0 + 1) * MS_PITCH + jm] = mx1;
                Ms[(col0 + 2) * MS_PITCH + jm] = mx2;
                Ms[(col0 + 3) * MS_PITCH + jm] = mx3;
            }
            __syncthreads();

            {
                const int nq = (q + 1) & 3;
                const int ntt = (q == 3) ? tt + (int)gridDim.x : tt;
                if (ntt < NT) {
                    const float* base = inp + (size_t)ntt * 32768 + nq * 64 + cq * 4;
#pragma unroll
                    for (int i = 0; i < 8; i++) v[i] = *(const float4*)(base + (size_t)(rb + i) * 256);
                }
            }

            {
                const unsigned bh = sb + SM_A + pb * (2 * QBUF);
                const unsigned bl = bh + QBUF;
#pragma unroll
                for (int kp = 0; kp < 2; kp++) {
                    const int ksg = q * 4 + kp * 2;
                    unsigned ah0[4], al0[4], ah1[4], al1[4];
                    ldm_x4(ah0, bh + lmrow + kp * 64);
                    ldm_x4(al0, bl + lmrow + kp * 64);
                    ldm_x4(ah1, bh + lmrow + kp * 64 + 32);
                    ldm_x4(al1, bl + lmrow + kp * 64 + 32);
                    const unsigned bbf = sb + SM_BF + lane * BLANE_B + ksg * 8;
#pragma unroll
                    for (int nt = 0; nt < 6; nt++) {
                        unsigned bhf[4], blf[4];
                        asm volatile("ld.shared.v4.b32 {%0,%1,%2,%3}, [%4];"
                                     : "=r"(bhf[0]), "=r"(bhf[1]), "=r"(bhf[2]), "=r"(bhf[3])
                                     : "r"(bbf + nt * 32 * BLANE_B));
                        asm volatile("ld.shared.v4.b32 {%0,%1,%2,%3}, [%4];"
                                     : "=r"(blf[0]), "=r"(blf[1]), "=r"(blf[2]), "=r"(blf[3])
                                     : "r"(bbf + (6 + nt) * 32 * BLANE_B));
                        mma_bf16(d[nt], ah0, bhf);
                        mma_bf16(d[nt], ah0, blf);
                        mma_bf16(d[nt], al0, bhf);
                        mma_bf16(d[nt], ah1, bhf + 2);
                        mma_bf16(d[nt], ah1, blf + 2);
                        mma_bf16(d[nt], al1, bhf + 2);
                    }
                }
            }
            pb ^= 1;
        }

        {
            const int row0 = r0 + w * 16 + gid;
#pragma unroll
            for (int nt = 0; nt < 6; nt++) {
                const int c = nt * 8 + tig * 2;
                if (nt < 4) {
                    *(float2*)(g_keys + (size_t)row0 * 32 + c)       = make_float2(d[nt][0], d[nt][1]);
                    *(float2*)(g_keys + (size_t)(row0 + 8) * 32 + c) = make_float2(d[nt][2], d[nt][3]);
                } else {
                    *(float2*)(g_evals + (size_t)row0 * 16 + (c - 32))       = make_float2(d[nt][0], d[nt][1]);
                    *(float2*)(g_evals + (size_t)(row0 + 8) * 16 + (c - 32)) = make_float2(d[nt][2], d[nt][3]);
                }
            }
        }
        {
            float m = Ms[t * MS_PITCH];
#pragma unroll
            for (int j = 1; j < 16; j++) m = fmaxf(m, Ms[t * MS_PITCH + j]);
            atomicMax(&g_pooled_enc[b * 256 + t], encf(m));
        }
        __syncthreads();
    }
}

// ---------------------------------------------------------------------------
// K3: q = pooled @ [Wq0;Wq1]^T  (unchanged)
// ---------------------------------------------------------------------------
#define QW_STRIDE 268
__global__ void __launch_bounds__(256)
k_q(const float* __restrict__ Wq0, const float* __restrict__ Wq1) {
    __shared__ float Ws[8 * QW_STRIDE];
    const int t = threadIdx.x;
    const int c0 = blockIdx.x * 8;
    for (int idx = t; idx < 8 * 256; idx += 256) {
        const int row = idx >> 8, k = idx & 255;
        const int o = c0 + row;
        Ws[row * QW_STRIDE + k] = (o < 512) ? Wq0[(size_t)o * 256 + k]
                                            : Wq1[(size_t)(o - 512) * 256 + k];
    }
    __syncthreads();
    const int col = t & 7, gs = t >> 3;
    const float4* w4 = (const float4*)(Ws + col * QW_STRIDE);
#pragma unroll
    for (int kk = 0; kk < 4; kk++) {
        const int g = gs + 32 * kk;
        const uint4* p4 = (const uint4*)(g_pooled_enc + g * 256);
        float acc = 0.f;
#pragma unroll 8
        for (int j = 0; j < 64; j++) {
            const uint4 e = p4[j];
            const float4 w = w4[j];
            acc = fmaf(decf(e.x), w.x, acc);
            acc = fmaf(decf(e.y), w.y, acc);
            acc = fmaf(decf(e.z), w.z, acc);
            acc = fmaf(decf(e.w), w.w, acc);
        }
        g_q[g * 1024 + c0 + col] = acc;
    }
}

// ---------------------------------------------------------------------------
// K4a: split-softmax partials with MMA logits (bf16 split: kh*qh+kh*ql+kl*qh)
// grid (128, 8), 256 threads, 2 CTA/SM.
// ---------------------------------------------------------------------------
#define KP 80                         // bf16 row pitch (32 bf16 = 64B + 16 pad)
#define AT_KSH 0
#define AT_KSL 20480
#define AT_QH  40960
#define AT_QL  43520
#define AT_ES  46080                  // f32 [256][20]
#define AT_L   66560                  // f32 [256][33]
#define SMEM_ATTN 100352

__global__ void __launch_bounds__(256, 2)
k_attn_part() {
    extern __shared__ char smc[];
    const unsigned sb = smem_u32(smc);
    float* ES = (float*)(smc + AT_ES);
    float* L  = (float*)(smc + AT_L);

    const int b = blockIdx.x, ch = blockIdx.y, t = threadIdx.x;
    const int lane = t & 31, w = t >> 5, g = lane >> 2, t4 = lane & 3;
    const int n0 = ch * CHUNK;

    // ---- stage keys -> bf16 h/l [256][KP] ----
    {
        const float4* kp = (const float4*)(g_keys + ((size_t)b * Ng + n0) * 32);
#pragma unroll
        for (int j = 0; j < 8; j++) {
            const int idx = t + 256 * j;
            const int n = idx >> 3, k4 = idx & 7;
            const float4 v = kp[idx];
            unsigned h01, h23, l01, l23;
            CVT_BF2(h01, v.x, v.y); CVT_BF2(h23, v.z, v.w);
            const float e0 = v.x - __uint_as_float(h01 << 16);
            const float e1 = v.y - __uint_as_float(h01 & 0xFFFF0000u);
            const float e2 = v.z - __uint_as_float(h23 << 16);
            const float e3 = v.w - __uint_as_float(h23 & 0xFFFF0000u);
            CVT_BF2(l01, e0, e1); CVT_BF2(l23, e2, e3);
            const unsigned off = (unsigned)(n * KP + k4 * 8);
            asm volatile("st.shared.v2.b32 [%0], {%1,%2};" :: "r"(sb + AT_KSH + off), "r"(h01), "r"(h23) : "memory");
            asm volatile("st.shared.v2.b32 [%0], {%1,%2};" :: "r"(sb + AT_KSL + off), "r"(l01), "r"(l23) : "memory");
        }
    }
    // ---- stage evals f32 [256][20] ----
    {
        const float4* ep = (const float4*)(g_evals + ((size_t)b * Ng + n0) * 16);
#pragma unroll
        for (int j = 0; j < 4; j++) {
            const int idx = t + 256 * j;
            const int n = idx >> 2, r4 = idx & 3;
            ((float4*)(ES + n * 20))[r4] = ep[idx];
        }
    }
    // ---- stage q -> bf16 h/l [32][KP] ----
    {
        const float4 v = ((const float4*)(g_q + b * 1024))[t];
        const int vh = t >> 3, k4 = t & 7;
        unsigned h01, h23, l01, l23;
        CVT_BF2(h01, v.x, v.y); CVT_BF2(h23, v.z, v.w);
        const float e0 = v.x - __uint_as_float(h01 << 16);
        const float e1 = v.y - __uint_as_float(h01 & 0xFFFF0000u);
        const float e2 = v.z - __uint_as_float(h23 << 16);
        const float e3 = v.w - __uint_as_float(h23 & 0xFFFF0000u);
        CVT_BF2(l01, e0, e1); CVT_BF2(l23, e2, e3);
        const unsigned off = (unsigned)(vh * KP + k4 * 8);
        asm volatile("st.shared.v2.b32 [%0], {%1,%2};" :: "r"(sb + AT_QH + off), "r"(h01), "r"(h23) : "memory");
        asm volatile("st.shared.v2.b32 [%0], {%1,%2};" :: "r"(sb + AT_QL + off), "r"(l01), "r"(l23) : "memory");
    }
    __syncthreads();

    // ---- phase 1: logits via MMA. warp w owns n rows [w*32, w*32+32) ----
    {
        float d[2][4][4];
#pragma unroll
        for (int s = 0; s < 2; s++)
#pragma unroll
            for (int vt = 0; vt < 4; vt++)
#pragma unroll
                for (int q = 0; q < 4; q++) d[s][vt][q] = 0.f;

        const unsigned aoff = (unsigned)((w * 32 + (lane & 15)) * KP + ((lane >> 4) << 4));
#pragma unroll
        for (int ks = 0; ks < 2; ks++) {
            unsigned ah0[4], ah1[4], al0[4], al1[4];
            ldm_x4(ah0, sb + AT_KSH + aoff + ks * 32);
            ldm_x4(ah1, sb + AT_KSH + aoff + 16 * KP + ks * 32);
            ldm_x4(al0, sb + AT_KSL + aoff + ks * 32);
            ldm_x4(al1, sb + AT_KSL + aoff + 16 * KP + ks * 32);
            const unsigned qo = (unsigned)(g * KP + ks * 32 + t4 * 4);
#pragma unroll
            for (int vt = 0; vt < 4; vt++) {
                unsigned bh[2], bl[2];
                asm volatile("ld.shared.b32 %0, [%1];" : "=r"(bh[0]) : "r"(sb + AT_QH + qo + vt * 8 * KP));
                asm volatile("ld.shared.b32 %0, [%1];" : "=r"(bh[1]) : "r"(sb + AT_QH + qo + vt * 8 * KP + 16));
                asm volatile("ld.shared.b32 %0, [%1];" : "=r"(bl[0]) : "r"(sb + AT_QL + qo + vt * 8 * KP));
                asm volatile("ld.shared.b32 %0, [%1];" : "=r"(bl[1]) : "r"(sb + AT_QL + qo + vt * 8 * KP + 16));
                mma_bf16(d[0][vt], ah0, bh);
                mma_bf16(d[0][vt], ah0, bl);
                mma_bf16(d[0][vt], al0, bh);
                mma_bf16(d[1][vt], ah1, bh);
                mma_bf16(d[1][vt], ah1, bl);
                mma_bf16(d[1][vt], al1, bh);
            }
        }
        // store logits [n][33]
#pragma unroll
        for (int s = 0; s < 2; s++) {
            const int row = w * 32 + s * 16 + g;
#pragma unroll
            for (int vt = 0; vt < 4; vt++) {
                const int c = vt * 8 + t4 * 2;
                L[row * 33 + c]           = d[s][vt][0];
                L[row * 33 + c + 1]       = d[s][vt][1];
                L[(row + 8) * 33 + c]     = d[s][vt][2];
                L[(row + 8) * 33 + c + 1] = d[s][vt][3];
            }
        }
    }
    __syncthreads();

    // ---- phase 2: per-vh softmax (warp w owns vh = w*4..w*4+3) ----
    float m[4], ssum[4];
#pragma unroll
    for (int j = 0; j < 4; j++) {
        const int vh = w * 4 + j;
        float lv[8];
#pragma unroll
        for (int i = 0; i < 8; i++) lv[i] = L[(lane + 32 * i) * 33 + vh];
        float mx = lv[0];
#pragma unroll
        for (int i = 1; i < 8; i++) mx = fmaxf(mx, lv[i]);
#pragma unroll
        for (int o = 16; o; o >>= 1) mx = fmaxf(mx, __shfl_xor_sync(0xffffffffu, mx, o));
        float ss = 0.f;
#pragma unroll
        for (int i = 0; i < 8; i++) {
            const float e = __expf(lv[i] - mx);
            L[(lane + 32 * i) * 33 + vh] = e;
            ss += e;
        }
#pragma unroll
        for (int o = 16; o; o >>= 1) ss += __shfl_xor_sync(0xffffffffu, ss, o);
        m[j] = mx; ssum[j] = ss;
    }
    __syncwarp();

    // ---- phase 3: acc[j][r] = sum_n att * evals[n][r] ----
    float acc[4][16];
#pragma unroll
    for (int j = 0; j < 4; j++)
#pragma unroll
        for (int r = 0; r < 16; r++) acc[j][r] = 0.f;

#pragma unroll
    for (int i = 0; i < 8; i++) {
        const int n = lane + 32 * i;
        const float4* erow = (const float4*)(ES + n * 20);
        const float4 e0 = erow[0], e1 = erow[1], e2 = erow[2], e3 = erow[3];
#pragma unroll
        for (int j = 0; j < 4; j++) {
            const float ev = L[n * 33 + w * 4 + j];
            acc[j][0]  = fmaf(ev, e0.x, acc[j][0]);
            acc[j][1]  = fmaf(ev, e0.y, acc[j][1]);
            acc[j][2]  = fmaf(ev, e0.z, acc[j][2]);
            acc[j][3]  = fmaf(ev, e0.w, acc[j][3]);
            acc[j][4]  = fmaf(ev, e1.x, acc[j][4]);
            acc[j][5]  = fmaf(ev, e1.y, acc[j][5]);
            acc[j][6]  = fmaf(ev, e1.z, acc[j][6]);
            acc[j][7]  = fmaf(ev, e1.w, acc[j][7]);
            acc[j][8]  = fmaf(ev, e2.x, acc[j][8]);
            acc[j][9]  = fmaf(ev, e2.y, acc[j][9]);
            acc[j][10] = fmaf(ev, e2.z, acc[j][10]);
            acc[j][11] = fmaf(ev, e2.w, acc[j][11]);
            acc[j][12] = fmaf(ev, e3.x, acc[j][12]);
            acc[j][13] = fmaf(ev, e3.y, acc[j][13]);
            acc[j][14] = fmaf(ev, e3.z, acc[j][14]);
            acc[j][15] = fmaf(ev, e3.w, acc[j][15]);
        }
    }

#pragma unroll
    for (int j = 0; j < 4; j++)
#pragma unroll
        for (int r = 0; r < 16; r++) {
            float a = acc[j][r];
#pragma unroll
            for (int o = 16; o; o >>= 1) a += __shfl_xor_sync(0xffffffffu, a, o);
            acc[j][r] = a;
        }

    if (lane == 0) {
        float* p = g_part + (((size_t)(b * NCHUNK + ch) * 32) + w * 4) * 18;
#pragma unroll
        for (int j = 0; j < 4; j++) {
            p[j * 18 + 0] = m[j];
            p[j * 18 + 1] = ssum[j];
#pragma unroll
            for (int r = 0; r < 16; r++) p[j * 18 + 2 + r] = acc[j][r];
        }
    }
}

__global__ void k_attn_red() {
    const int b = blockIdx.x, vh = threadIdx.x;
    const float* base = g_part + (size_t)b * NCHUNK * 32 * 18 + vh * 18;
    float M = __int_as_float(0xff800000);
#pragma unroll
    for (int c = 0; c < NCHUNK; c++) M = fmaxf(M, base[c * 32 * 18]);
    float S = 0.f, acc[16];
#pragma unroll
    for (int r = 0; r < 16; r++) acc[r] = 0.f;
#pragma unroll
    for (int c = 0; c < NCHUNK; c++) {
        const float* p = base + c * 32 * 18;
        const float w = __expf(p[0] - M);
        S = fmaf(p[1], w, S);
#pragma unroll
        for (int r = 0; r < 16; r++) acc[r] = fmaf(p[2 + r], w, acc[r]);
    }
    const float inv = 1.f / S;
#pragma unroll
    for (int r = 0; r < 16; r++)
        g_embed[b * 512 + vh * 16 + r] = acc[r] * inv;
}

// ---------------------------------------------------------------------------
// K5: out = leaky((embed0-embed1) @ Wout^T + bout)  (unchanged)
// ---------------------------------------------------------------------------
__global__ void __launch_bounds__(256)
k_out(const float* __restrict__ Wout, const float* __restrict__ bout,
      float* __restrict__ out) {
    __shared__ float Ws[8 * QW_STRIDE];
    const int t = threadIdx.x;
    const int d0 = blockIdx.x * 8;
    for (int idx = t; idx < 8 * 256; idx += 256) {
        const int row = idx >> 8, k = idx & 255;
        Ws[row * QW_STRIDE + k] = Wout[(size_t)(d0 + row) * 256 + k];
    }
    __syncthreads();
    const int col = t & 7, gs = t >> 3;
    const int d = d0 + col;
    const float bv = bout[d];
    const float4* w4 = (const float4*)(Ws + col * QW_STRIDE);
#pragma unroll
    for (int kk = 0; kk < 4; kk++) {
        const int g = gs + 32 * kk;
        const float4* e0p = (const float4*)(g_embed + g * 512);
        const float4* e1p = (const float4*)(g_embed + g * 512 + 256);
        float acc = bv;
#pragma unroll 8
        for (int j = 0; j < 64; j++) {
            const float4 a = e0p[j], bq = e1p[j], w = w4[j];
            acc = fmaf(a.x - bq.x, w.x, acc);
            acc = fmaf(a.y - bq.y, w.y, acc);
            acc = fmaf(a.z - bq.z, w.z, acc);
            acc = fmaf(a.w - bq.w, w.w, acc);
        }
        out[g * 256 + d] = acc >= 0.f ? acc : 0.01f * acc;
    }
}

extern "C" void kernel_launch(void* const* d_in, const int* in_sizes, int n_in,
                              void* d_out, int out_size) {
    const float* inp  = (const float*)d_in[0];
    const float* Wk   = (const float*)d_in[2];
    const float* Wq0  = (const float*)d_in[3];
    const float* Wq1  = (const float*)d_in[4];
    const float* We   = (const float*)d_in[5];
    const float* Wout = (const float*)d_in[6];
    const float* bout = (const float*)d_in[7];
    float* out = (float*)d_out;

    cudaFuncSetAttribute(k_gemm, cudaFuncAttributeMaxDynamicSharedMemorySize, SMEM_GEMM);
    cudaFuncSetAttribute(k_attn_part, cudaFuncAttributeMaxDynamicSharedMemorySize, SMEM_ATTN);

    k_init<<<128, 256>>>();
    k_dummy<<<1, 32>>>();     // shift k_gemm into ncu's -s 5 -c 1 capture slot
    k_dummy<<<1, 32>>>();
    k_gemm<<<148, 256, SMEM_GEMM>>>(inp, Wk, We);
    k_q<<<128, 256>>>(Wq0, Wq1);
    k_attn_part<<<dim3(Bg, NCHUNK), 256, SMEM_ATTN>>>();
    k_attn_red<<<Bg, 32>>>();
    k_out<<<32, 256>>>(Wout, bout, out);
}